// round 2
// baseline (speedup 1.0000x reference)
#include <cuda_runtime.h>
#include <cstdint>

#define SLEN 128
#define BSZ  16
#define EMB  512
#define NHEAD 8
#define HDIM 64
#define BH   (BSZ*NHEAD)   // 128
#define NEG_INF (-1e9f)
#define SCALING 0.125f     // 1/sqrt(64)

// ---------------- scratch (device globals; no runtime alloc) ----------------
__device__ float g_q[BH*SLEN*HDIM];        // [b][i][d]   4 MB
__device__ float g_k[BH*SLEN*HDIM];        // [b][j][d]   4 MB
__device__ float g_v[BH*SLEN*HDIM];        // [b][j][d]   4 MB
__device__ float g_r[SLEN*BSZ*EMB];        // [m=i*16+n][e] 4 MB
__device__ float g_qW[BH*SLEN*EMB];        // [b][i][e]  33.5 MB
__device__ float g_aw[BH*SLEN*SLEN];       // [b][i][j]   8 MB
__device__ float g_s[BH*SLEN*EMB];         // [b][i][e]  33.5 MB
__device__ float g_attn[SLEN*BSZ*EMB];     // [m][e]      4 MB

// ---------------- K1: fused projections  C = X(2048x512) @ W^T --------------
// cols 0..511 -> q, 512..1023 -> k, 1024..1535 -> v, 1536..2047 -> r(skip)
__global__ __launch_bounds__(256) void k1_proj(const float* __restrict__ x,
                                               const float* __restrict__ Wq,
                                               const float* __restrict__ Wk,
                                               const float* __restrict__ Wv,
                                               const float* __restrict__ Wskip) {
    __shared__ float As[8][128];
    __shared__ float Bs[8][128];
    const int m0 = blockIdx.y * 128;
    const int c0 = blockIdx.x * 128;
    const int sel = c0 >> 9;
    const float* W = (sel == 0) ? Wq : (sel == 1) ? Wk : (sel == 2) ? Wv : Wskip;
    const int e0 = c0 & 511;

    const int t  = threadIdx.x;
    const int ty = t >> 4, tx = t & 15;
    const int lr = t >> 1;           // 0..127
    const int lc = (t & 1) * 4;      // 0 or 4

    float acc[8][8];
#pragma unroll
    for (int a = 0; a < 8; a++)
#pragma unroll
        for (int b = 0; b < 8; b++) acc[a][b] = 0.f;

    for (int k0 = 0; k0 < 512; k0 += 8) {
        float4 a4 = *(const float4*)(x + (size_t)(m0 + lr) * 512 + k0 + lc);
        float4 b4 = *(const float4*)(W + (size_t)(e0 + lr) * 512 + k0 + lc);
        As[lc + 0][lr] = a4.x; As[lc + 1][lr] = a4.y;
        As[lc + 2][lr] = a4.z; As[lc + 3][lr] = a4.w;
        Bs[lc + 0][lr] = b4.x; Bs[lc + 1][lr] = b4.y;
        Bs[lc + 2][lr] = b4.z; Bs[lc + 3][lr] = b4.w;
        __syncthreads();
#pragma unroll
        for (int kk = 0; kk < 8; kk++) {
            float a[8], b[8];
            *(float4*)(a)     = *(float4*)&As[kk][ty * 8];
            *(float4*)(a + 4) = *(float4*)&As[kk][ty * 8 + 4];
            *(float4*)(b)     = *(float4*)&Bs[kk][tx * 8];
            *(float4*)(b + 4) = *(float4*)&Bs[kk][tx * 8 + 4];
#pragma unroll
            for (int p = 0; p < 8; p++)
#pragma unroll
                for (int q = 0; q < 8; q++) acc[p][q] += a[p] * b[q];
        }
        __syncthreads();
    }

    // epilogue: scatter into head-split layouts
    const int ecol = e0 + tx * 8;           // base e for this thread's 8 cols
    const int h = ecol >> 6;
    const int d0 = ecol & 63;
#pragma unroll
    for (int ry = 0; ry < 8; ry++) {
        const int m = m0 + ty * 8 + ry;
        const int i = m >> 4, n = m & 15;
        if (sel == 3) {
            float* dst = g_r + (size_t)m * 512 + ecol;
            *(float4*)dst       = *(float4*)&acc[ry][0];
            *(float4*)(dst + 4) = *(float4*)&acc[ry][4];
        } else {
            float* base = (sel == 0) ? g_q : (sel == 1) ? g_k : g_v;
            float* dst = base + ((size_t)(n * 8 + h) * 128 + i) * 64 + d0;
            *(float4*)dst       = *(float4*)&acc[ry][0];
            *(float4*)(dst + 4) = *(float4*)&acc[ry][4];
        }
    }
}

// ---------------- K2: qW[b][i][e] = sum_d q[b][i][d] * Wknow[h*64+d][e] -----
__global__ __launch_bounds__(128) void k2_qw(const float* __restrict__ Wknow) {
    const int b  = blockIdx.x;      // 0..127
    const int i0 = blockIdx.y * 16; // 8 tiles of 16 i
    const int h  = b & 7;
    const int t  = threadIdx.x;     // 128

    __shared__ float q_s[16][64];
    for (int u = 0; u < 8; u++) {
        int idx = t + 128 * u;      // 0..1023
        int ii = idx >> 6, d = idx & 63;
        q_s[ii][d] = g_q[((size_t)b * 128 + i0 + ii) * 64 + d];
    }
    __syncthreads();

    float acc[16][4];
#pragma unroll
    for (int ii = 0; ii < 16; ii++)
#pragma unroll
        for (int c = 0; c < 4; c++) acc[ii][c] = 0.f;

    const int e = 4 * t;
    for (int d = 0; d < 64; d++) {
        float4 w4 = *(const float4*)(Wknow + (size_t)(h * 64 + d) * 512 + e);
#pragma unroll
        for (int ii = 0; ii < 16; ii++) {
            float qv = q_s[ii][d];
            acc[ii][0] += qv * w4.x; acc[ii][1] += qv * w4.y;
            acc[ii][2] += qv * w4.z; acc[ii][3] += qv * w4.w;
        }
    }
#pragma unroll
    for (int ii = 0; ii < 16; ii++) {
        float4 o; o.x = acc[ii][0]; o.y = acc[ii][1]; o.z = acc[ii][2]; o.w = acc[ii][3];
        *(float4*)&g_qW[((size_t)b * 128 + i0 + ii) * 512 + e] = o;
    }
}

// ---------------- K3: logits = (q.k + know.qW)*scale, mask, softmax ---------
// one block per (n, i); streams know rows once.
__global__ __launch_bounds__(256) void k3_logits(const float* __restrict__ know,
                                                 const int* __restrict__ mask) {
    const int n = blockIdx.x >> 7;
    const int i = blockIdx.x & 127;
    const int t = threadIdx.x;
    const int w = t >> 5, l = t & 31;

    __shared__ float qW_s[8 * 512];
    __shared__ float q_s[8 * 64];
    __shared__ float logit_s[8 * 128];

    for (int idx = t; idx < 4096; idx += 256) {
        int h = idx >> 9, e = idx & 511;
        qW_s[idx] = g_qW[((size_t)(n * 8 + h) * 128 + i) * 512 + e];
    }
    for (int idx = t; idx < 512; idx += 256) {
        int h = idx >> 6, d = idx & 63;
        q_s[idx] = g_q[((size_t)(n * 8 + h) * 128 + i) * 64 + d];
    }
    __syncthreads();

    const int hk = l >> 2;            // head handled by this lane for q.k part
    const int db = (l & 3) * 4;

    for (int rr = 0; rr < 16; rr++) {
        const int j = w * 16 + rr;
        float acc[8];
#pragma unroll
        for (int h = 0; h < 8; h++) acc[h] = 0.f;

        const float* kn = know + ((size_t)(n * 16384 + i * 128 + j)) * 512;
#pragma unroll
        for (int u = 0; u < 4; u++) {
            float4 kv = *(const float4*)(kn + 128 * u + 4 * l);
#pragma unroll
            for (int h = 0; h < 8; h++) {
                float4 qw = *(float4*)&qW_s[h * 512 + 128 * u + 4 * l];
                acc[h] += kv.x * qw.x + kv.y * qw.y + kv.z * qw.z + kv.w * qw.w;
            }
        }
        // q . k  (lane covers 16 of the 64 dims of one head)
        {
            const float* kp = g_k + ((size_t)(n * 8 + hk) * 128 + j) * 64;
#pragma unroll
            for (int u = 0; u < 4; u++) {
                float4 k4 = *(const float4*)(kp + db + 16 * u);
                float4 q4 = *(float4*)&q_s[hk * 64 + db + 16 * u];
                acc[hk] += k4.x * q4.x + k4.y * q4.y + k4.z * q4.z + k4.w * q4.w;
            }
        }
        // butterfly all-reduce over lanes for all 8 heads
#pragma unroll
        for (int off = 16; off; off >>= 1)
#pragma unroll
            for (int h = 0; h < 8; h++)
                acc[h] += __shfl_xor_sync(0xffffffffu, acc[h], off);

        if (l < 8) {
            int mv = mask[((size_t)(n * 8 + l) * 128 + i) * 128 + j];
            logit_s[l * 128 + j] = mv ? acc[l] * SCALING : NEG_INF;
        }
    }
    __syncthreads();

    // softmax: warp w handles head w
    {
        const int h = w;
        float v[4];
#pragma unroll
        for (int c = 0; c < 4; c++) v[c] = logit_s[h * 128 + l + 32 * c];
        float m = fmaxf(fmaxf(v[0], v[1]), fmaxf(v[2], v[3]));
#pragma unroll
        for (int off = 16; off; off >>= 1)
            m = fmaxf(m, __shfl_xor_sync(0xffffffffu, m, off));
        float sum = 0.f;
#pragma unroll
        for (int c = 0; c < 4; c++) { v[c] = __expf(v[c] - m); sum += v[c]; }
#pragma unroll
        for (int off = 16; off; off >>= 1)
            sum += __shfl_xor_sync(0xffffffffu, sum, off);
        float inv = 1.f / sum;
#pragma unroll
        for (int c = 0; c < 4; c++)
            g_aw[((size_t)(n * 8 + h) * 128 + i) * 128 + l + 32 * c] = v[c] * inv;
    }
}

// ---------------- K4a: s[b][i][e] = sum_j aw[b][i][j]*know[n][ij][e] --------
__global__ __launch_bounds__(256) void k4a_s(const float* __restrict__ know) {
    const int n = blockIdx.x >> 7;
    const int i = blockIdx.x & 127;
    const int t = threadIdx.x;

    __shared__ float awT[128 * 8];   // [j][h]
    for (int idx = t; idx < 1024; idx += 256) {
        int h = idx >> 7, j = idx & 127;
        awT[j * 8 + h] = g_aw[((size_t)(n * 8 + h) * 128 + i) * 128 + j];
    }
    __syncthreads();

    float acc[16];
#pragma unroll
    for (int c = 0; c < 16; c++) acc[c] = 0.f;

    const float* kb = know + (size_t)(n * 16384 + i * 128) * 512;
    const int e = 2 * t;
    for (int j = 0; j < 128; j++) {
        float2 kn2 = *(const float2*)(kb + (size_t)j * 512 + e);
        float4 a0 = *(float4*)&awT[j * 8];
        float4 a1 = *(float4*)&awT[j * 8 + 4];
        acc[0]  += a0.x * kn2.x; acc[1]  += a0.x * kn2.y;
        acc[2]  += a0.y * kn2.x; acc[3]  += a0.y * kn2.y;
        acc[4]  += a0.z * kn2.x; acc[5]  += a0.z * kn2.y;
        acc[6]  += a0.w * kn2.x; acc[7]  += a0.w * kn2.y;
        acc[8]  += a1.x * kn2.x; acc[9]  += a1.x * kn2.y;
        acc[10] += a1.y * kn2.x; acc[11] += a1.y * kn2.y;
        acc[12] += a1.z * kn2.x; acc[13] += a1.z * kn2.y;
        acc[14] += a1.w * kn2.x; acc[15] += a1.w * kn2.y;
    }
#pragma unroll
    for (int h = 0; h < 8; h++) {
        float2 o; o.x = acc[2 * h]; o.y = acc[2 * h + 1];
        *(float2*)&g_s[((size_t)(n * 8 + h) * 128 + i) * 512 + e] = o;
    }
}

// ---------------- K4b: attn = aw@v + s@Wknow_h^T  (combined K=640 GEMM) -----
// grid: (32 row-tiles of 64, 8 heads). BM=64, BN=64, BK=16.
__global__ __launch_bounds__(256) void k4b_attn(const float* __restrict__ Wknow) {
    __shared__ float As[16][64];
    __shared__ float Bs[16][64];
    const int h = blockIdx.y;
    const int r0 = blockIdx.x * 64;
    const int n = r0 >> 7;
    const int i0 = r0 & 127;
    const int t = threadIdx.x;
    const int ty = t >> 4, tx = t & 15;

    float acc[4][4];
#pragma unroll
    for (int a = 0; a < 4; a++)
#pragma unroll
        for (int b = 0; b < 4; b++) acc[a][b] = 0.f;

    for (int k0 = 0; k0 < 640; k0 += 16) {
        // A tile
        {
            const int rr = t >> 2, kq = (t & 3) * 4;
            const int ii = i0 + rr;
            float4 a4;
            if (k0 < 128)
                a4 = *(const float4*)&g_aw[((size_t)(n * 8 + h) * 128 + ii) * 128 + k0 + kq];
            else
                a4 = *(const float4*)&g_s[((size_t)(n * 8 + h) * 128 + ii) * 512 + (k0 - 128) + kq];
            As[kq + 0][rr] = a4.x; As[kq + 1][rr] = a4.y;
            As[kq + 2][rr] = a4.z; As[kq + 3][rr] = a4.w;
        }
        // B tile
        if (k0 < 128) {
            const int kr = t >> 4, dq = (t & 15) * 4;
            float4 b4 = *(const float4*)&g_v[((size_t)(n * 8 + h) * 128 + (k0 + kr)) * 64 + dq];
            *(float4*)&Bs[kr][dq] = b4;
        } else {
            const int d = t >> 2, eq = (t & 3) * 4;
            float4 w4 = *(const float4*)(Wknow + (size_t)(h * 64 + d) * 512 + (k0 - 128) + eq);
            Bs[eq + 0][d] = w4.x; Bs[eq + 1][d] = w4.y;
            Bs[eq + 2][d] = w4.z; Bs[eq + 3][d] = w4.w;
        }
        __syncthreads();
#pragma unroll
        for (int kk = 0; kk < 16; kk++) {
            float4 a4 = *(float4*)&As[kk][ty * 4];
            float4 b4 = *(float4*)&Bs[kk][tx * 4];
            acc[0][0] += a4.x * b4.x; acc[0][1] += a4.x * b4.y; acc[0][2] += a4.x * b4.z; acc[0][3] += a4.x * b4.w;
            acc[1][0] += a4.y * b4.x; acc[1][1] += a4.y * b4.y; acc[1][2] += a4.y * b4.z; acc[1][3] += a4.y * b4.w;
            acc[2][0] += a4.z * b4.x; acc[2][1] += a4.z * b4.y; acc[2][2] += a4.z * b4.z; acc[2][3] += a4.z * b4.w;
            acc[3][0] += a4.w * b4.x; acc[3][1] += a4.w * b4.y; acc[3][2] += a4.w * b4.z; acc[3][3] += a4.w * b4.w;
        }
        __syncthreads();
    }
#pragma unroll
    for (int ry = 0; ry < 4; ry++) {
        const int ii = i0 + ty * 4 + ry;
        float* dst = g_attn + ((size_t)ii * 16 + n) * 512 + h * 64 + tx * 4;
        *(float4*)dst = *(float4*)&acc[ry][0];
    }
}

// ---------------- K5: gating  out = g*r + (1-g)*attn ------------------------
__global__ __launch_bounds__(128) void k5_gate(const float* __restrict__ Wbeta,
                                               float* __restrict__ out) {
    const int m = blockIdx.x;   // 0..2047  (= i*16+n)
    const int t = threadIdx.x;  // 128
    const int w = t >> 5, l = t & 31;
    __shared__ float red[4];

    const float* a = g_attn + (size_t)m * 512;
    const float* r = g_r + (size_t)m * 512;

    float z = 0.f;
#pragma unroll
    for (int c = 0; c < 4; c++) {
        int e = t + 128 * c;
        float av = a[e], rv = r[e];
        z += Wbeta[e] * av + Wbeta[512 + e] * rv + Wbeta[1024 + e] * (av - rv);
    }
#pragma unroll
    for (int off = 16; off; off >>= 1)
        z += __shfl_xor_sync(0xffffffffu, z, off);
    if (l == 0) red[w] = z;
    __syncthreads();
    float zt = red[0] + red[1] + red[2] + red[3];
    float g = 1.f / (1.f + __expf(-zt));

#pragma unroll
    for (int c = 0; c < 4; c++) {
        int e = t + 128 * c;
        out[(size_t)m * 512 + e] = g * r[e] + (1.f - g) * a[e];
    }
}

// ---------------- launch -----------------------------------------------------
extern "C" void kernel_launch(void* const* d_in, const int* in_sizes, int n_in,
                              void* d_out, int out_size) {
    const float* x     = (const float*)d_in[0];
    const float* know  = (const float*)d_in[1];
    const int*   mask  = (const int*)d_in[2];
    const float* Wq    = (const float*)d_in[3];
    const float* Wk    = (const float*)d_in[4];
    const float* Wv    = (const float*)d_in[5];
    const float* Wknow = (const float*)d_in[6];
    const float* Wskip = (const float*)d_in[7];
    const float* Wbeta = (const float*)d_in[8];
    float* out = (float*)d_out;

    k1_proj<<<dim3(16, 16), 256>>>(x, Wq, Wk, Wv, Wskip);
    k2_qw<<<dim3(128, 8), 128>>>(Wknow);
    k3_logits<<<2048, 256>>>(know, mask);
    k4a_s<<<2048, 256>>>(know);
    k4b_attn<<<dim3(32, 8), 256>>>(Wknow);
    k5_gate<<<2048, 128>>>(Wbeta, out);
}

// round 3
// speedup vs baseline: 1.2638x; 1.2638x over previous
#include <cuda_runtime.h>
#include <cstdint>

#define SLEN 128
#define BSZ  16
#define EMB  512
#define NHEAD 8
#define HDIM 64
#define BH   (BSZ*NHEAD)   // 128
#define NEG_INF (-1e9f)
#define SCALING 0.125f     // 1/sqrt(64)

// ---------------- scratch (device globals; no runtime alloc) ----------------
__device__ float g_q[BH*SLEN*HDIM];        // [b][i][d]   4 MB
__device__ float g_k[BH*SLEN*HDIM];        // [b][j][d]   4 MB
__device__ float g_v[BH*SLEN*HDIM];        // [b][j][d]   4 MB
__device__ float g_r[SLEN*BSZ*EMB];        // [m=i*16+n][e] 4 MB
__device__ float g_qW[BH*SLEN*EMB];        // [b][i][e]  33.5 MB
__device__ float g_aw[BH*SLEN*SLEN];       // [b][i][j]   8 MB (qk base, then aw)
__device__ float g_s[BH*SLEN*EMB];         // [b][i][e]  33.5 MB
__device__ float g_attn[SLEN*BSZ*EMB];     // [m][e]      4 MB

// ---------------- K1: fused projections  C = X(2048x512) @ W^T --------------
__global__ __launch_bounds__(256) void k1_proj(const float* __restrict__ x,
                                               const float* __restrict__ Wq,
                                               const float* __restrict__ Wk,
                                               const float* __restrict__ Wv,
                                               const float* __restrict__ Wskip) {
    __shared__ float As[8][128];
    __shared__ float Bs[8][128];
    const int m0 = blockIdx.y * 128;
    const int c0 = blockIdx.x * 128;
    const int sel = c0 >> 9;
    const float* W = (sel == 0) ? Wq : (sel == 1) ? Wk : (sel == 2) ? Wv : Wskip;
    const int e0 = c0 & 511;

    const int t  = threadIdx.x;
    const int ty = t >> 4, tx = t & 15;
    const int lr = t >> 1;
    const int lc = (t & 1) * 4;

    float acc[8][8];
#pragma unroll
    for (int a = 0; a < 8; a++)
#pragma unroll
        for (int b = 0; b < 8; b++) acc[a][b] = 0.f;

    for (int k0 = 0; k0 < 512; k0 += 8) {
        float4 a4 = *(const float4*)(x + (size_t)(m0 + lr) * 512 + k0 + lc);
        float4 b4 = *(const float4*)(W + (size_t)(e0 + lr) * 512 + k0 + lc);
        As[lc + 0][lr] = a4.x; As[lc + 1][lr] = a4.y;
        As[lc + 2][lr] = a4.z; As[lc + 3][lr] = a4.w;
        Bs[lc + 0][lr] = b4.x; Bs[lc + 1][lr] = b4.y;
        Bs[lc + 2][lr] = b4.z; Bs[lc + 3][lr] = b4.w;
        __syncthreads();
#pragma unroll
        for (int kk = 0; kk < 8; kk++) {
            float a[8], b[8];
            *(float4*)(a)     = *(float4*)&As[kk][ty * 8];
            *(float4*)(a + 4) = *(float4*)&As[kk][ty * 8 + 4];
            *(float4*)(b)     = *(float4*)&Bs[kk][tx * 8];
            *(float4*)(b + 4) = *(float4*)&Bs[kk][tx * 8 + 4];
#pragma unroll
            for (int p = 0; p < 8; p++)
#pragma unroll
                for (int q = 0; q < 8; q++) acc[p][q] += a[p] * b[q];
        }
        __syncthreads();
    }

    const int ecol = e0 + tx * 8;
    const int h = ecol >> 6;
    const int d0 = ecol & 63;
#pragma unroll
    for (int ry = 0; ry < 8; ry++) {
        const int m = m0 + ty * 8 + ry;
        const int i = m >> 4, n = m & 15;
        if (sel == 3) {
            float* dst = g_r + (size_t)m * 512 + ecol;
            *(float4*)dst       = *(float4*)&acc[ry][0];
            *(float4*)(dst + 4) = *(float4*)&acc[ry][4];
        } else {
            float* base = (sel == 0) ? g_q : (sel == 1) ? g_k : g_v;
            float* dst = base + ((size_t)(n * 8 + h) * 128 + i) * 64 + d0;
            *(float4*)dst       = *(float4*)&acc[ry][0];
            *(float4*)(dst + 4) = *(float4*)&acc[ry][4];
        }
    }
}

// ---------------- K2: qW[b][i][e] = sum_d q[b][i][d] * Wknow[h*64+d][e] -----
__global__ __launch_bounds__(128) void k2_qw(const float* __restrict__ Wknow) {
    const int b  = blockIdx.x;
    const int i0 = blockIdx.y * 16;
    const int h  = b & 7;
    const int t  = threadIdx.x;

    __shared__ float q_s[16][64];
    for (int u = 0; u < 8; u++) {
        int idx = t + 128 * u;
        int ii = idx >> 6, d = idx & 63;
        q_s[ii][d] = g_q[((size_t)b * 128 + i0 + ii) * 64 + d];
    }
    __syncthreads();

    float acc[16][4];
#pragma unroll
    for (int ii = 0; ii < 16; ii++)
#pragma unroll
        for (int c = 0; c < 4; c++) acc[ii][c] = 0.f;

    const int e = 4 * t;
    for (int d = 0; d < 64; d++) {
        float4 w4 = *(const float4*)(Wknow + (size_t)(h * 64 + d) * 512 + e);
#pragma unroll
        for (int ii = 0; ii < 16; ii++) {
            float qv = q_s[ii][d];
            acc[ii][0] += qv * w4.x; acc[ii][1] += qv * w4.y;
            acc[ii][2] += qv * w4.z; acc[ii][3] += qv * w4.w;
        }
    }
#pragma unroll
    for (int ii = 0; ii < 16; ii++) {
        float4 o; o.x = acc[ii][0]; o.y = acc[ii][1]; o.z = acc[ii][2]; o.w = acc[ii][3];
        *(float4*)&g_qW[((size_t)b * 128 + i0 + ii) * 512 + e] = o;
    }
}

// ---------------- K3pre: qk[b][i][j] = q . k  (base logits, unscaled) -------
// one block per b (=n*8+h). 128x128x64 GEMM from smem-transposed tiles.
__global__ __launch_bounds__(256) void k3pre() {
    const int b = blockIdx.x;
    __shared__ float qT[32][128];
    __shared__ float kT[32][128];
    const int t = threadIdx.x, ty = t >> 4, tx = t & 15;

    float acc[8][8];
#pragma unroll
    for (int p = 0; p < 8; p++)
#pragma unroll
        for (int q = 0; q < 8; q++) acc[p][q] = 0.f;

    for (int d0 = 0; d0 < 64; d0 += 32) {
#pragma unroll
        for (int u = 0; u < 4; u++) {
            int ii = (t >> 3) + 32 * u;
            int d4 = (t & 7) * 4;
            float4 a = *(const float4*)&g_q[((size_t)b * 128 + ii) * 64 + d0 + d4];
            qT[d4 + 0][ii] = a.x; qT[d4 + 1][ii] = a.y;
            qT[d4 + 2][ii] = a.z; qT[d4 + 3][ii] = a.w;
            float4 bb = *(const float4*)&g_k[((size_t)b * 128 + ii) * 64 + d0 + d4];
            kT[d4 + 0][ii] = bb.x; kT[d4 + 1][ii] = bb.y;
            kT[d4 + 2][ii] = bb.z; kT[d4 + 3][ii] = bb.w;
        }
        __syncthreads();
#pragma unroll
        for (int d = 0; d < 32; d++) {
            float a[8], bl[8];
            *(float4*)(a)      = *(float4*)&qT[d][ty * 8];
            *(float4*)(a + 4)  = *(float4*)&qT[d][ty * 8 + 4];
            *(float4*)(bl)     = *(float4*)&kT[d][tx * 8];
            *(float4*)(bl + 4) = *(float4*)&kT[d][tx * 8 + 4];
#pragma unroll
            for (int p = 0; p < 8; p++)
#pragma unroll
                for (int q = 0; q < 8; q++) acc[p][q] += a[p] * bl[q];
        }
        __syncthreads();
    }
#pragma unroll
    for (int p = 0; p < 8; p++) {
        float* dst = &g_aw[((size_t)b * 128 + ty * 8 + p) * 128 + tx * 8];
        *(float4*)dst       = *(float4*)&acc[p][0];
        *(float4*)(dst + 4) = *(float4*)&acc[p][4];
    }
}

// ---------------- K34: fused logits(know) + softmax + s-accum ---------------
// one block per (n,i). 8 warps: warp w -> e-chunk c=w&3, j-half jh=w>>2.
// pass1: logits += know . qW   (qW in registers, butterfly reduce)
// softmax (scale, mask) -> p in smem + g_aw
// pass2 (know re-read, L2-hot): s[h][e] = sum_j p[h][j]*know[j][e]
__global__ __launch_bounds__(256) void k34_fused(const float* __restrict__ know,
                                                 const int* __restrict__ mask) {
    const int n = blockIdx.x >> 7;
    const int i = blockIdx.x & 127;
    const int t = threadIdx.x, w = t >> 5, l = t & 31;
    const int c = w & 3, jh = w >> 2;
    const int e0 = 128 * c + 4 * l;

    __shared__ float logit_s[8 * 128];   // 4 KB: qk base -> logits -> p
    __shared__ float s_s[8 * 512];       // 16 KB: jh=1 partials

    // init logits from qk base (k3pre output)
    {
        const int h = t >> 5, j0 = (t & 31) * 4;
        float4 v = *(const float4*)&g_aw[(((size_t)(n * 8 + h) * 128 + i)) * 128 + j0];
        *(float4*)&logit_s[h * 128 + j0] = v;
    }

    // qW in registers: 8 heads x float4 at this lane's e-slice
    float4 qw[8];
#pragma unroll
    for (int h = 0; h < 8; h++)
        qw[h] = *(const float4*)&g_qW[(((size_t)(n * 8 + h) * 128 + i)) * 512 + e0];

    __syncthreads();

    const float* knb = know + ((size_t)n * 16384 + (size_t)i * 128) * 512 + e0;

    // ---- pass 1: logits ----
    for (int jj = 0; jj < 64; jj++) {
        const int j = (jh << 6) + jj;
        float4 kn = *(const float4*)(knb + (size_t)j * 512);
        float v[8];
#pragma unroll
        for (int h = 0; h < 8; h++)
            v[h] = kn.x * qw[h].x + kn.y * qw[h].y + kn.z * qw[h].z + kn.w * qw[h].w;

        // value-halving butterfly: 8 vals over 32 lanes
#pragma unroll
        for (int h = 0; h < 4; h++) {
            float give = (l & 16) ? v[h] : v[h + 4];
            float keep = (l & 16) ? v[h + 4] : v[h];
            v[h] = keep + __shfl_xor_sync(0xffffffffu, give, 16);
        }
#pragma unroll
        for (int h = 0; h < 2; h++) {
            float give = (l & 8) ? v[h] : v[h + 2];
            float keep = (l & 8) ? v[h + 2] : v[h];
            v[h] = keep + __shfl_xor_sync(0xffffffffu, give, 8);
        }
        {
            float give = (l & 4) ? v[0] : v[1];
            float keep = (l & 4) ? v[1] : v[0];
            v[0] = keep + __shfl_xor_sync(0xffffffffu, give, 4);
        }
        v[0] += __shfl_xor_sync(0xffffffffu, v[0], 2);
        v[0] += __shfl_xor_sync(0xffffffffu, v[0], 1);
        if ((l & 3) == 0) {
            const int h = ((l >> 4) & 1) * 4 + ((l >> 3) & 1) * 2 + ((l >> 2) & 1);
            atomicAdd(&logit_s[h * 128 + j], v[0]);
        }
    }
    __syncthreads();

    // ---- softmax: warp w handles head w ----
    {
        const int h = w;
        const size_t mb = (((size_t)(n * 8 + h) * 128 + i)) * 128;
        float vv[4];
#pragma unroll
        for (int cc = 0; cc < 4; cc++) {
            const int j = l + 32 * cc;
            float lg = logit_s[h * 128 + j] * SCALING;
            vv[cc] = mask[mb + j] ? lg : NEG_INF;
        }
        float m = fmaxf(fmaxf(vv[0], vv[1]), fmaxf(vv[2], vv[3]));
#pragma unroll
        for (int off = 16; off; off >>= 1)
            m = fmaxf(m, __shfl_xor_sync(0xffffffffu, m, off));
        float sum = 0.f;
#pragma unroll
        for (int cc = 0; cc < 4; cc++) { vv[cc] = __expf(vv[cc] - m); sum += vv[cc]; }
#pragma unroll
        for (int off = 16; off; off >>= 1)
            sum += __shfl_xor_sync(0xffffffffu, sum, off);
        const float inv = 1.f / sum;
#pragma unroll
        for (int cc = 0; cc < 4; cc++) {
            const int j = l + 32 * cc;
            const float p = vv[cc] * inv;
            logit_s[h * 128 + j] = p;
            g_aw[mb + j] = p;
        }
    }
    __syncthreads();

    // ---- pass 2: s accumulation (know re-read, mostly L2 hits) ----
    float4 s4[8];
#pragma unroll
    for (int h = 0; h < 8; h++) s4[h] = make_float4(0.f, 0.f, 0.f, 0.f);

    for (int jj = 0; jj < 64; jj++) {
        const int j = (jh << 6) + jj;
        float4 kn = *(const float4*)(knb + (size_t)j * 512);
#pragma unroll
        for (int h = 0; h < 8; h++) {
            const float p = logit_s[h * 128 + j];
            s4[h].x += p * kn.x; s4[h].y += p * kn.y;
            s4[h].z += p * kn.z; s4[h].w += p * kn.w;
        }
    }

    if (jh == 1) {
#pragma unroll
        for (int h = 0; h < 8; h++)
            *(float4*)&s_s[h * 512 + e0] = s4[h];
    }
    __syncthreads();
    if (jh == 0) {
#pragma unroll
        for (int h = 0; h < 8; h++) {
            float4 o = *(float4*)&s_s[h * 512 + e0];
            o.x += s4[h].x; o.y += s4[h].y; o.z += s4[h].z; o.w += s4[h].w;
            *(float4*)&g_s[(((size_t)(n * 8 + h) * 128 + i)) * 512 + e0] = o;
        }
    }
}

// ---------------- K4b: attn = aw@v + s@Wknow_h^T  (combined K=640 GEMM) -----
__global__ __launch_bounds__(256) void k4b_attn(const float* __restrict__ Wknow) {
    __shared__ float As[16][64];
    __shared__ float Bs[16][64];
    const int h = blockIdx.y;
    const int r0 = blockIdx.x * 64;
    const int n = r0 >> 7;
    const int i0 = r0 & 127;
    const int t = threadIdx.x;
    const int ty = t >> 4, tx = t & 15;

    float acc[4][4];
#pragma unroll
    for (int a = 0; a < 4; a++)
#pragma unroll
        for (int b = 0; b < 4; b++) acc[a][b] = 0.f;

    for (int k0 = 0; k0 < 640; k0 += 16) {
        {
            const int rr = t >> 2, kq = (t & 3) * 4;
            const int ii = i0 + rr;
            float4 a4;
            if (k0 < 128)
                a4 = *(const float4*)&g_aw[((size_t)(n * 8 + h) * 128 + ii) * 128 + k0 + kq];
            else
                a4 = *(const float4*)&g_s[((size_t)(n * 8 + h) * 128 + ii) * 512 + (k0 - 128) + kq];
            As[kq + 0][rr] = a4.x; As[kq + 1][rr] = a4.y;
            As[kq + 2][rr] = a4.z; As[kq + 3][rr] = a4.w;
        }
        if (k0 < 128) {
            const int kr = t >> 4, dq = (t & 15) * 4;
            float4 b4 = *(const float4*)&g_v[((size_t)(n * 8 + h) * 128 + (k0 + kr)) * 64 + dq];
            *(float4*)&Bs[kr][dq] = b4;
        } else {
            const int d = t >> 2, eq = (t & 3) * 4;
            float4 w4 = *(const float4*)(Wknow + (size_t)(h * 64 + d) * 512 + (k0 - 128) + eq);
            Bs[eq + 0][d] = w4.x; Bs[eq + 1][d] = w4.y;
            Bs[eq + 2][d] = w4.z; Bs[eq + 3][d] = w4.w;
        }
        __syncthreads();
#pragma unroll
        for (int kk = 0; kk < 16; kk++) {
            float4 a4 = *(float4*)&As[kk][ty * 4];
            float4 b4 = *(float4*)&Bs[kk][tx * 4];
            acc[0][0] += a4.x * b4.x; acc[0][1] += a4.x * b4.y; acc[0][2] += a4.x * b4.z; acc[0][3] += a4.x * b4.w;
            acc[1][0] += a4.y * b4.x; acc[1][1] += a4.y * b4.y; acc[1][2] += a4.y * b4.z; acc[1][3] += a4.y * b4.w;
            acc[2][0] += a4.z * b4.x; acc[2][1] += a4.z * b4.y; acc[2][2] += a4.z * b4.z; acc[2][3] += a4.z * b4.w;
            acc[3][0] += a4.w * b4.x; acc[3][1] += a4.w * b4.y; acc[3][2] += a4.w * b4.z; acc[3][3] += a4.w * b4.w;
        }
        __syncthreads();
    }
#pragma unroll
    for (int ry = 0; ry < 4; ry++) {
        const int ii = i0 + ty * 4 + ry;
        float* dst = g_attn + ((size_t)ii * 16 + n) * 512 + h * 64 + tx * 4;
        *(float4*)dst = *(float4*)&acc[ry][0];
    }
}

// ---------------- K5: gating  out = g*r + (1-g)*attn ------------------------
__global__ __launch_bounds__(128) void k5_gate(const float* __restrict__ Wbeta,
                                               float* __restrict__ out) {
    const int m = blockIdx.x;
    const int t = threadIdx.x;
    const int w = t >> 5, l = t & 31;
    __shared__ float red[4];

    const float* a = g_attn + (size_t)m * 512;
    const float* r = g_r + (size_t)m * 512;

    float z = 0.f;
#pragma unroll
    for (int c = 0; c < 4; c++) {
        int e = t + 128 * c;
        float av = a[e], rv = r[e];
        z += Wbeta[e] * av + Wbeta[512 + e] * rv + Wbeta[1024 + e] * (av - rv);
    }
#pragma unroll
    for (int off = 16; off; off >>= 1)
        z += __shfl_xor_sync(0xffffffffu, z, off);
    if (l == 0) red[w] = z;
    __syncthreads();
    float zt = red[0] + red[1] + red[2] + red[3];
    float g = 1.f / (1.f + __expf(-zt));

#pragma unroll
    for (int c = 0; c < 4; c++) {
        int e = t + 128 * c;
        out[(size_t)m * 512 + e] = g * r[e] + (1.f - g) * a[e];
    }
}

// ---------------- launch -----------------------------------------------------
extern "C" void kernel_launch(void* const* d_in, const int* in_sizes, int n_in,
                              void* d_out, int out_size) {
    const float* x     = (const float*)d_in[0];
    const float* know  = (const float*)d_in[1];
    const int*   mask  = (const int*)d_in[2];
    const float* Wq    = (const float*)d_in[3];
    const float* Wk    = (const float*)d_in[4];
    const float* Wv    = (const float*)d_in[5];
    const float* Wknow = (const float*)d_in[6];
    const float* Wskip = (const float*)d_in[7];
    const float* Wbeta = (const float*)d_in[8];
    float* out = (float*)d_out;

    k1_proj<<<dim3(16, 16), 256>>>(x, Wq, Wk, Wv, Wskip);
    k2_qw<<<dim3(128, 8), 128>>>(Wknow);
    k3pre<<<128, 256>>>();
    k34_fused<<<2048, 256>>>(know, mask);
    k4b_attn<<<dim3(32, 8), 256>>>(Wknow);
    k5_gate<<<2048, 128>>>(Wbeta, out);
}

// round 4
// speedup vs baseline: 1.3208x; 1.0451x over previous
#include <cuda_runtime.h>
#include <cstdint>

#define SLEN 128
#define BSZ  16
#define EMB  512
#define NHEAD 8
#define HDIM 64
#define BH   (BSZ*NHEAD)   // 128
#define NEG_INF (-1e9f)
#define SCALING 0.125f     // 1/sqrt(64)

// ---- f32x2 packed math (Blackwell) ----
#define FMA2(d, a, b) asm("fma.rn.f32x2 %0, %1, %2, %0;" : "+l"(d) : "l"(a), "l"(b))
#define PACK2(u, lo, hi) asm("mov.b64 %0, {%1, %2};" : "=l"(u) : "f"(lo), "f"(hi))
#define UNPACK2(lo, hi, u) asm("mov.b64 {%0, %1}, %2;" : "=f"(lo), "=f"(hi) : "l"(u))

typedef unsigned long long ull_t;

// ---------------- scratch (device globals; no runtime alloc) ----------------
__device__ float g_q[BH*SLEN*HDIM];        // [b][i][d]
__device__ float g_k[BH*SLEN*HDIM];        // [b][j][d]
__device__ float g_v[BH*SLEN*HDIM];        // [b][j][d]
__device__ float g_r[SLEN*BSZ*EMB];        // [m][e]
__device__ float g_qW[BH*SLEN*EMB];        // [b][i][e]
__device__ float g_aw[BH*SLEN*SLEN];       // [b][i][j]  (qk base, then normalized aw)
__device__ float g_s[BH*SLEN*EMB];         // [b][i][e]
__device__ float g_attn[SLEN*BSZ*EMB];     // [m][e]

// ---------------- K1: fused projections  C = X(2048x512) @ W^T --------------
__global__ __launch_bounds__(256) void k1_proj(const float* __restrict__ x,
                                               const float* __restrict__ Wq,
                                               const float* __restrict__ Wk,
                                               const float* __restrict__ Wv,
                                               const float* __restrict__ Wskip) {
    __shared__ float As[8][128];
    __shared__ float Bs[8][128];
    const int m0 = blockIdx.y * 128;
    const int c0 = blockIdx.x * 128;
    const int sel = c0 >> 9;
    const float* W = (sel == 0) ? Wq : (sel == 1) ? Wk : (sel == 2) ? Wv : Wskip;
    const int e0 = c0 & 511;

    const int t  = threadIdx.x;
    const int ty = t >> 4, tx = t & 15;
    const int lr = t >> 1;
    const int lc = (t & 1) * 4;

    ull_t acc2[8][4];
#pragma unroll
    for (int a = 0; a < 8; a++)
#pragma unroll
        for (int b = 0; b < 4; b++) acc2[a][b] = 0ull;

    for (int k0 = 0; k0 < 512; k0 += 8) {
        float4 a4 = *(const float4*)(x + (size_t)(m0 + lr) * 512 + k0 + lc);
        float4 b4 = *(const float4*)(W + (size_t)(e0 + lr) * 512 + k0 + lc);
        As[lc + 0][lr] = a4.x; As[lc + 1][lr] = a4.y;
        As[lc + 2][lr] = a4.z; As[lc + 3][lr] = a4.w;
        Bs[lc + 0][lr] = b4.x; Bs[lc + 1][lr] = b4.y;
        Bs[lc + 2][lr] = b4.z; Bs[lc + 3][lr] = b4.w;
        __syncthreads();
#pragma unroll
        for (int kk = 0; kk < 8; kk++) {
            float a[8];
            *(float4*)(a)     = *(float4*)&As[kk][ty * 8];
            *(float4*)(a + 4) = *(float4*)&As[kk][ty * 8 + 4];
            ulonglong2 bA = *(ulonglong2*)&Bs[kk][tx * 8];
            ulonglong2 bB = *(ulonglong2*)&Bs[kk][tx * 8 + 4];
#pragma unroll
            for (int p = 0; p < 8; p++) {
                ull_t ap; PACK2(ap, a[p], a[p]);
                FMA2(acc2[p][0], ap, bA.x);
                FMA2(acc2[p][1], ap, bA.y);
                FMA2(acc2[p][2], ap, bB.x);
                FMA2(acc2[p][3], ap, bB.y);
            }
        }
        __syncthreads();
    }

    const int ecol = e0 + tx * 8;
    const int h = ecol >> 6;
    const int d0 = ecol & 63;
#pragma unroll
    for (int ry = 0; ry < 8; ry++) {
        const int m = m0 + ty * 8 + ry;
        const int i = m >> 4, n = m & 15;
        float o[8];
#pragma unroll
        for (int q = 0; q < 4; q++) UNPACK2(o[2*q], o[2*q+1], acc2[ry][q]);
        if (sel == 3) {
            float* dst = g_r + (size_t)m * 512 + ecol;
            *(float4*)dst       = *(float4*)&o[0];
            *(float4*)(dst + 4) = *(float4*)&o[4];
        } else {
            float* base = (sel == 0) ? g_q : (sel == 1) ? g_k : g_v;
            float* dst = base + ((size_t)(n * 8 + h) * 128 + i) * 64 + d0;
            *(float4*)dst       = *(float4*)&o[0];
            *(float4*)(dst + 4) = *(float4*)&o[4];
        }
    }
}

// ---------------- K2: qW[b][i][e] = sum_d q[b][i][d] * Wknow[h*64+d][e] -----
__global__ __launch_bounds__(128) void k2_qw(const float* __restrict__ Wknow) {
    const int b  = blockIdx.x;
    const int i0 = blockIdx.y * 16;
    const int h  = b & 7;
    const int t  = threadIdx.x;

    __shared__ float q_s[16][64];
    for (int u = 0; u < 8; u++) {
        int idx = t + 128 * u;
        int ii = idx >> 6, d = idx & 63;
        q_s[ii][d] = g_q[((size_t)b * 128 + i0 + ii) * 64 + d];
    }
    __syncthreads();

    float acc[16][4];
#pragma unroll
    for (int ii = 0; ii < 16; ii++)
#pragma unroll
        for (int c = 0; c < 4; c++) acc[ii][c] = 0.f;

    const int e = 4 * t;
    for (int d = 0; d < 64; d++) {
        float4 w4 = *(const float4*)(Wknow + (size_t)(h * 64 + d) * 512 + e);
#pragma unroll
        for (int ii = 0; ii < 16; ii++) {
            float qv = q_s[ii][d];
            acc[ii][0] += qv * w4.x; acc[ii][1] += qv * w4.y;
            acc[ii][2] += qv * w4.z; acc[ii][3] += qv * w4.w;
        }
    }
#pragma unroll
    for (int ii = 0; ii < 16; ii++) {
        float4 o; o.x = acc[ii][0]; o.y = acc[ii][1]; o.z = acc[ii][2]; o.w = acc[ii][3];
        *(float4*)&g_qW[((size_t)b * 128 + i0 + ii) * 512 + e] = o;
    }
}

// ---------------- K3pre: qk[b][i][j] = q . k  (base logits, unscaled) -------
__global__ __launch_bounds__(256) void k3pre() {
    const int b = blockIdx.x;
    __shared__ float qT[32][128];
    __shared__ float kT[32][128];
    const int t = threadIdx.x, ty = t >> 4, tx = t & 15;

    float acc[8][8];
#pragma unroll
    for (int p = 0; p < 8; p++)
#pragma unroll
        for (int q = 0; q < 8; q++) acc[p][q] = 0.f;

    for (int d0 = 0; d0 < 64; d0 += 32) {
#pragma unroll
        for (int u = 0; u < 4; u++) {
            int ii = (t >> 3) + 32 * u;
            int d4 = (t & 7) * 4;
            float4 a = *(const float4*)&g_q[((size_t)b * 128 + ii) * 64 + d0 + d4];
            qT[d4 + 0][ii] = a.x; qT[d4 + 1][ii] = a.y;
            qT[d4 + 2][ii] = a.z; qT[d4 + 3][ii] = a.w;
            float4 bb = *(const float4*)&g_k[((size_t)b * 128 + ii) * 64 + d0 + d4];
            kT[d4 + 0][ii] = bb.x; kT[d4 + 1][ii] = bb.y;
            kT[d4 + 2][ii] = bb.z; kT[d4 + 3][ii] = bb.w;
        }
        __syncthreads();
#pragma unroll
        for (int d = 0; d < 32; d++) {
            float a[8], bl[8];
            *(float4*)(a)      = *(float4*)&qT[d][ty * 8];
            *(float4*)(a + 4)  = *(float4*)&qT[d][ty * 8 + 4];
            *(float4*)(bl)     = *(float4*)&kT[d][tx * 8];
            *(float4*)(bl + 4) = *(float4*)&kT[d][tx * 8 + 4];
#pragma unroll
            for (int p = 0; p < 8; p++)
#pragma unroll
                for (int q = 0; q < 8; q++) acc[p][q] += a[p] * bl[q];
        }
        __syncthreads();
    }
#pragma unroll
    for (int p = 0; p < 8; p++) {
        float* dst = &g_aw[((size_t)b * 128 + ty * 8 + p) * 128 + tx * 8];
        *(float4*)dst       = *(float4*)&acc[p][0];
        *(float4*)(dst + 4) = *(float4*)&acc[p][4];
    }
}

// ---------------- K34: ONE-PASS logits + exp + s-accum over know ------------
// Block = (n,i). know streamed ONCE through 16KB smem tiles of TJ=8 rows.
// No max-subtraction softmax (|logit*scale| <~ 12 -> exp safe); normalize at end.
#define TJ 8
__global__ __launch_bounds__(256, 2) void k34_onepass(const float* __restrict__ know,
                                                      const int* __restrict__ mask) {
    __shared__ float kn_s[TJ][512];      // 16 KB
    __shared__ float qW_s[8][512];       // 16 KB
    __shared__ float p_s[8][128];        // 4 KB (unnormalized p)
    __shared__ float qk_s[8][128];       // 4 KB (q.k base from k3pre)
    __shared__ unsigned char m8[8][128]; // 1 KB
    __shared__ float inv_s[8];

    const int n = blockIdx.x >> 7;
    const int i = blockIdx.x & 127;
    const int t = threadIdx.x, w = t >> 5, l = t & 31;

    // ---- preload qW (4096 floats), qk base (1024), mask (1024) ----
#pragma unroll
    for (int u = 0; u < 4; u++) {
        int c = t + 256 * u;
        int h = c >> 7, e = (c & 127) << 2;
        *(float4*)&qW_s[h][e] =
            *(const float4*)&g_qW[(((size_t)(n * 8 + h) * 128 + i)) * 512 + e];
    }
    {
        int h = t >> 5, j0 = (t & 31) << 2;
        *(float4*)&qk_s[h][j0] =
            *(const float4*)&g_aw[(((size_t)(n * 8 + h) * 128 + i)) * 128 + j0];
        int4 mm = *(const int4*)&mask[(((size_t)(n * 8 + h) * 128 + i)) * 128 + j0];
        uchar4 mb;
        mb.x = (unsigned char)(mm.x != 0); mb.y = (unsigned char)(mm.y != 0);
        mb.z = (unsigned char)(mm.z != 0); mb.w = (unsigned char)(mm.w != 0);
        *(uchar4*)&m8[h][j0] = mb;
    }

    const float* knbase = know + ((size_t)n * 16384 + (size_t)i * 128) * 512;

    // persistent s accumulators: this thread owns heads [4g,4g+4), e-chunk e0
    const int g = t >> 7;
    const int ec = t & 127;
    const int e0 = ec << 2;
    ull_t accv[4][2];
#pragma unroll
    for (int hh = 0; hh < 4; hh++) { accv[hh][0] = 0ull; accv[hh][1] = 0ull; }

    // prefetch tile 0
    float4 pf[4];
#pragma unroll
    for (int u = 0; u < 4; u++) {
        int c = t + 256 * u;
        pf[u] = *(const float4*)(knbase + (size_t)(c >> 7) * 512 + ((c & 127) << 2));
    }
#pragma unroll
    for (int u = 0; u < 4; u++) {
        int c = t + 256 * u;
        *(float4*)&kn_s[c >> 7][(c & 127) << 2] = pf[u];
    }

#pragma unroll 1
    for (int tt = 0; tt < 16; tt++) {
        __syncthreads();   // tile visible

        // ---- phase 1: logits for j = 8*tt + w (one warp per row) ----
        {
            ull_t acc2[8];
#pragma unroll
            for (int h = 0; h < 8; h++) acc2[h] = 0ull;
            const ulonglong2* kr = (const ulonglong2*)&kn_s[w][0];
#pragma unroll
            for (int u = 0; u < 4; u++) {
                ulonglong2 kv = kr[l + 32 * u];
#pragma unroll
                for (int h = 0; h < 8; h++) {
                    ulonglong2 qv = *(const ulonglong2*)&qW_s[h][(l + 32 * u) << 2];
                    FMA2(acc2[h], kv.x, qv.x);
                    FMA2(acc2[h], kv.y, qv.y);
                }
            }
            float v[8];
#pragma unroll
            for (int h = 0; h < 8; h++) {
                float lo, hi; UNPACK2(lo, hi, acc2[h]); v[h] = lo + hi;
            }
            // value-halving butterfly: 8 vals over 32 lanes
#pragma unroll
            for (int h = 0; h < 4; h++) {
                float give = (l & 16) ? v[h] : v[h + 4];
                float keep = (l & 16) ? v[h + 4] : v[h];
                v[h] = keep + __shfl_xor_sync(0xffffffffu, give, 16);
            }
#pragma unroll
            for (int h = 0; h < 2; h++) {
                float give = (l & 8) ? v[h] : v[h + 2];
                float keep = (l & 8) ? v[h + 2] : v[h];
                v[h] = keep + __shfl_xor_sync(0xffffffffu, give, 8);
            }
            {
                float give = (l & 4) ? v[0] : v[1];
                float keep = (l & 4) ? v[1] : v[0];
                v[0] = keep + __shfl_xor_sync(0xffffffffu, give, 4);
            }
            v[0] += __shfl_xor_sync(0xffffffffu, v[0], 2);
            v[0] += __shfl_xor_sync(0xffffffffu, v[0], 1);
            if ((l & 3) == 0) {
                const int h = ((l >> 4) & 1) * 4 + ((l >> 3) & 1) * 2 + ((l >> 2) & 1);
                const int j = tt * TJ + w;
                float lg = (v[0] + qk_s[h][j]) * SCALING;
                p_s[h][j] = m8[h][j] ? __expf(lg) : 0.f;
            }
        }

        // prefetch next tile while p_s propagates
        if (tt < 15) {
#pragma unroll
            for (int u = 0; u < 4; u++) {
                int c = t + 256 * u;
                pf[u] = *(const float4*)(knbase + (size_t)((tt + 1) * TJ + (c >> 7)) * 512
                                         + ((c & 127) << 2));
            }
        }
        __syncthreads();   // p_s visible

        // ---- phase 3: s accumulation from the SAME smem tile ----
        {
            const int h0 = g * 4;
            const int jb = tt * TJ;
#pragma unroll
            for (int jl = 0; jl < TJ; jl++) {
                ulonglong2 kv = *(const ulonglong2*)&kn_s[jl][e0];
#pragma unroll
                for (int hh = 0; hh < 4; hh++) {
                    float p = p_s[h0 + hh][jb + jl];
                    ull_t p2; PACK2(p2, p, p);
                    FMA2(accv[hh][0], p2, kv.x);
                    FMA2(accv[hh][1], p2, kv.y);
                }
            }
        }
        __syncthreads();   // done reading kn_s

        if (tt < 15) {
#pragma unroll
            for (int u = 0; u < 4; u++) {
                int c = t + 256 * u;
                *(float4*)&kn_s[c >> 7][(c & 127) << 2] = pf[u];
            }
        }
    }

    // ---- normalization: warp w sums p_s over head w ----
    {
        float s = 0.f;
#pragma unroll
        for (int c = 0; c < 4; c++) s += p_s[w][l + 32 * c];
#pragma unroll
        for (int off = 16; off; off >>= 1)
            s += __shfl_xor_sync(0xffffffffu, s, off);
        if (l == 0) inv_s[w] = 1.f / s;
    }
    __syncthreads();

    // ---- write s (normalized) ----
    {
        const int h0 = g * 4;
#pragma unroll
        for (int hh = 0; hh < 4; hh++) {
            float inv = inv_s[h0 + hh];
            float4 o;
            UNPACK2(o.x, o.y, accv[hh][0]);
            UNPACK2(o.z, o.w, accv[hh][1]);
            o.x *= inv; o.y *= inv; o.z *= inv; o.w *= inv;
            *(float4*)&g_s[(((size_t)(n * 8 + h0 + hh) * 128 + i)) * 512 + e0] = o;
        }
    }
    // ---- write normalized aw ----
#pragma unroll
    for (int u = 0; u < 4; u++) {
        int c = t + 256 * u;
        int h = c >> 7, j = c & 127;
        g_aw[(((size_t)(n * 8 + h) * 128 + i)) * 128 + j] = p_s[h][j] * inv_s[h];
    }
}

// ---------------- K4b: attn = aw@v + s@Wknow_h^T  (combined K=640 GEMM) -----
__global__ __launch_bounds__(256) void k4b_attn(const float* __restrict__ Wknow) {
    __shared__ float As[16][64];
    __shared__ float Bs[16][64];
    const int h = blockIdx.y;
    const int r0 = blockIdx.x * 64;
    const int n = r0 >> 7;
    const int i0 = r0 & 127;
    const int t = threadIdx.x;
    const int ty = t >> 4, tx = t & 15;

    float acc[4][4];
#pragma unroll
    for (int a = 0; a < 4; a++)
#pragma unroll
        for (int b = 0; b < 4; b++) acc[a][b] = 0.f;

    for (int k0 = 0; k0 < 640; k0 += 16) {
        {
            const int rr = t >> 2, kq = (t & 3) * 4;
            const int ii = i0 + rr;
            float4 a4;
            if (k0 < 128)
                a4 = *(const float4*)&g_aw[((size_t)(n * 8 + h) * 128 + ii) * 128 + k0 + kq];
            else
                a4 = *(const float4*)&g_s[((size_t)(n * 8 + h) * 128 + ii) * 512 + (k0 - 128) + kq];
            As[kq + 0][rr] = a4.x; As[kq + 1][rr] = a4.y;
            As[kq + 2][rr] = a4.z; As[kq + 3][rr] = a4.w;
        }
        if (k0 < 128) {
            const int kr = t >> 4, dq = (t & 15) * 4;
            float4 b4 = *(const float4*)&g_v[((size_t)(n * 8 + h) * 128 + (k0 + kr)) * 64 + dq];
            *(float4*)&Bs[kr][dq] = b4;
        } else {
            const int d = t >> 2, eq = (t & 3) * 4;
            float4 w4 = *(const float4*)(Wknow + (size_t)(h * 64 + d) * 512 + (k0 - 128) + eq);
            Bs[eq + 0][d] = w4.x; Bs[eq + 1][d] = w4.y;
            Bs[eq + 2][d] = w4.z; Bs[eq + 3][d] = w4.w;
        }
        __syncthreads();
#pragma unroll
        for (int kk = 0; kk < 16; kk++) {
            float4 a4 = *(float4*)&As[kk][ty * 4];
            float4 b4 = *(float4*)&Bs[kk][tx * 4];
            acc[0][0] += a4.x * b4.x; acc[0][1] += a4.x * b4.y; acc[0][2] += a4.x * b4.z; acc[0][3] += a4.x * b4.w;
            acc[1][0] += a4.y * b4.x; acc[1][1] += a4.y * b4.y; acc[1][2] += a4.y * b4.z; acc[1][3] += a4.y * b4.w;
            acc[2][0] += a4.z * b4.x; acc[2][1] += a4.z * b4.y; acc[2][2] += a4.z * b4.z; acc[2][3] += a4.z * b4.w;
            acc[3][0] += a4.w * b4.x; acc[3][1] += a4.w * b4.y; acc[3][2] += a4.w * b4.z; acc[3][3] += a4.w * b4.w;
        }
        __syncthreads();
    }
#pragma unroll
    for (int ry = 0; ry < 4; ry++) {
        const int ii = i0 + ty * 4 + ry;
        float* dst = g_attn + ((size_t)ii * 16 + n) * 512 + h * 64 + tx * 4;
        *(float4*)dst = *(float4*)&acc[ry][0];
    }
}

// ---------------- K5: gating  out = g*r + (1-g)*attn ------------------------
__global__ __launch_bounds__(128) void k5_gate(const float* __restrict__ Wbeta,
                                               float* __restrict__ out) {
    const int m = blockIdx.x;
    const int t = threadIdx.x;
    const int w = t >> 5, l = t & 31;
    __shared__ float red[4];

    const float* a = g_attn + (size_t)m * 512;
    const float* r = g_r + (size_t)m * 512;

    float z = 0.f;
#pragma unroll
    for (int c = 0; c < 4; c++) {
        int e = t + 128 * c;
        float av = a[e], rv = r[e];
        z += Wbeta[e] * av + Wbeta[512 + e] * rv + Wbeta[1024 + e] * (av - rv);
    }
#pragma unroll
    for (int off = 16; off; off >>= 1)
        z += __shfl_xor_sync(0xffffffffu, z, off);
    if (l == 0) red[w] = z;
    __syncthreads();
    float zt = red[0] + red[1] + red[2] + red[3];
    float g = 1.f / (1.f + __expf(-zt));

#pragma unroll
    for (int c = 0; c < 4; c++) {
        int e = t + 128 * c;
        out[(size_t)m * 512 + e] = g * r[e] + (1.f - g) * a[e];
    }
}

// ---------------- launch -----------------------------------------------------
extern "C" void kernel_launch(void* const* d_in, const int* in_sizes, int n_in,
                              void* d_out, int out_size) {
    const float* x     = (const float*)d_in[0];
    const float* know  = (const float*)d_in[1];
    const int*   mask  = (const int*)d_in[2];
    const float* Wq    = (const float*)d_in[3];
    const float* Wk    = (const float*)d_in[4];
    const float* Wv    = (const float*)d_in[5];
    const float* Wknow = (const float*)d_in[6];
    const float* Wskip = (const float*)d_in[7];
    const float* Wbeta = (const float*)d_in[8];
    float* out = (float*)d_out;

    k1_proj<<<dim3(16, 16), 256>>>(x, Wq, Wk, Wv, Wskip);
    k2_qw<<<dim3(128, 8), 128>>>(Wknow);
    k3pre<<<128, 256>>>();
    k34_onepass<<<2048, 256>>>(know, mask);
    k4b_attn<<<dim3(32, 8), 256>>>(Wknow);
    k5_gate<<<2048, 128>>>(Wbeta, out);
}

// round 5
// speedup vs baseline: 1.4211x; 1.0759x over previous
#include <cuda_runtime.h>
#include <cstdint>

#define SLEN 128
#define BSZ  16
#define EMB  512
#define NHEAD 8
#define HDIM 64
#define BH   (BSZ*NHEAD)   // 128
#define NEG_INF (-1e9f)
#define SCALING 0.125f     // 1/sqrt(64)

// ---- f32x2 packed math (Blackwell) ----
#define FMA2(d, a, b) asm("fma.rn.f32x2 %0, %1, %2, %0;" : "+l"(d) : "l"(a), "l"(b))
#define PACK2(u, lo, hi) asm("mov.b64 %0, {%1, %2};" : "=l"(u) : "f"(lo), "f"(hi))
#define UNPACK2(lo, hi, u) asm("mov.b64 {%0, %1}, %2;" : "=f"(lo), "=f"(hi) : "l"(u))

typedef unsigned long long ull_t;

// ---------------- scratch (device globals; no runtime alloc) ----------------
__device__ float g_q[BH*SLEN*HDIM];        // [b][i][d]
__device__ float g_k[BH*SLEN*HDIM];        // [b][j][d]
__device__ float g_v[BH*SLEN*HDIM];        // [b][j][d]
__device__ float g_r[SLEN*BSZ*EMB];        // [m][e]
__device__ float g_qW[BH*SLEN*EMB];        // [b][i][e]
__device__ float g_aw[BH*SLEN*SLEN];       // [b][i][j]  (qk base, then normalized aw)
__device__ float g_s[BH*SLEN*EMB];         // [b][i][e]
__device__ float g_attn[SLEN*BSZ*EMB];     // [m][e]

// ---------------- K1: fused projections  C = X(2048x512) @ W^T --------------
__global__ __launch_bounds__(256) void k1_proj(const float* __restrict__ x,
                                               const float* __restrict__ Wq,
                                               const float* __restrict__ Wk,
                                               const float* __restrict__ Wv,
                                               const float* __restrict__ Wskip) {
    __shared__ float As[16][128];
    __shared__ float Bs[16][128];
    const int m0 = blockIdx.y * 128;
    const int c0 = blockIdx.x * 128;
    const int sel = c0 >> 9;
    const float* W = (sel == 0) ? Wq : (sel == 1) ? Wk : (sel == 2) ? Wv : Wskip;
    const int e0 = c0 & 511;

    const int t  = threadIdx.x;
    const int ty = t >> 4, tx = t & 15;
    const int lr = t >> 1;
    const int lc = (t & 1) * 8;

    ull_t acc2[8][4];
#pragma unroll
    for (int a = 0; a < 8; a++)
#pragma unroll
        for (int b = 0; b < 4; b++) acc2[a][b] = 0ull;

    for (int k0 = 0; k0 < 512; k0 += 16) {
        float4 a0 = *(const float4*)(x + (size_t)(m0 + lr) * 512 + k0 + lc);
        float4 a1 = *(const float4*)(x + (size_t)(m0 + lr) * 512 + k0 + lc + 4);
        float4 b0 = *(const float4*)(W + (size_t)(e0 + lr) * 512 + k0 + lc);
        float4 b1 = *(const float4*)(W + (size_t)(e0 + lr) * 512 + k0 + lc + 4);
        As[lc + 0][lr] = a0.x; As[lc + 1][lr] = a0.y;
        As[lc + 2][lr] = a0.z; As[lc + 3][lr] = a0.w;
        As[lc + 4][lr] = a1.x; As[lc + 5][lr] = a1.y;
        As[lc + 6][lr] = a1.z; As[lc + 7][lr] = a1.w;
        Bs[lc + 0][lr] = b0.x; Bs[lc + 1][lr] = b0.y;
        Bs[lc + 2][lr] = b0.z; Bs[lc + 3][lr] = b0.w;
        Bs[lc + 4][lr] = b1.x; Bs[lc + 5][lr] = b1.y;
        Bs[lc + 6][lr] = b1.z; Bs[lc + 7][lr] = b1.w;
        __syncthreads();
#pragma unroll
        for (int kk = 0; kk < 16; kk++) {
            float a[8];
            *(float4*)(a)     = *(float4*)&As[kk][ty * 8];
            *(float4*)(a + 4) = *(float4*)&As[kk][ty * 8 + 4];
            ulonglong2 bA = *(ulonglong2*)&Bs[kk][tx * 8];
            ulonglong2 bB = *(ulonglong2*)&Bs[kk][tx * 8 + 4];
#pragma unroll
            for (int p = 0; p < 8; p++) {
                ull_t ap; PACK2(ap, a[p], a[p]);
                FMA2(acc2[p][0], ap, bA.x);
                FMA2(acc2[p][1], ap, bA.y);
                FMA2(acc2[p][2], ap, bB.x);
                FMA2(acc2[p][3], ap, bB.y);
            }
        }
        __syncthreads();
    }

    const int ecol = e0 + tx * 8;
    const int h = ecol >> 6;
    const int d0 = ecol & 63;
#pragma unroll
    for (int ry = 0; ry < 8; ry++) {
        const int m = m0 + ty * 8 + ry;
        const int i = m >> 4, n = m & 15;
        float o[8];
#pragma unroll
        for (int q = 0; q < 4; q++) UNPACK2(o[2*q], o[2*q+1], acc2[ry][q]);
        if (sel == 3) {
            float* dst = g_r + (size_t)m * 512 + ecol;
            *(float4*)dst       = *(float4*)&o[0];
            *(float4*)(dst + 4) = *(float4*)&o[4];
        } else {
            float* base = (sel == 0) ? g_q : (sel == 1) ? g_k : g_v;
            float* dst = base + ((size_t)(n * 8 + h) * 128 + i) * 64 + d0;
            *(float4*)dst       = *(float4*)&o[0];
            *(float4*)(dst + 4) = *(float4*)&o[4];
        }
    }
}

// ---------------- K2: qW[b][i][e] = sum_d q[b][i][d] * Wknow[h*64+d][e] -----
__global__ __launch_bounds__(128) void k2_qw(const float* __restrict__ Wknow) {
    const int b  = blockIdx.x;
    const int i0 = blockIdx.y * 16;
    const int h  = b & 7;
    const int t  = threadIdx.x;

    __shared__ float q_s[16][64];
    for (int u = 0; u < 8; u++) {
        int idx = t + 128 * u;
        int ii = idx >> 6, d = idx & 63;
        q_s[ii][d] = g_q[((size_t)b * 128 + i0 + ii) * 64 + d];
    }
    __syncthreads();

    float acc[16][4];
#pragma unroll
    for (int ii = 0; ii < 16; ii++)
#pragma unroll
        for (int c = 0; c < 4; c++) acc[ii][c] = 0.f;

    const int e = 4 * t;
    for (int d = 0; d < 64; d++) {
        float4 w4 = *(const float4*)(Wknow + (size_t)(h * 64 + d) * 512 + e);
#pragma unroll
        for (int ii = 0; ii < 16; ii++) {
            float qv = q_s[ii][d];
            acc[ii][0] += qv * w4.x; acc[ii][1] += qv * w4.y;
            acc[ii][2] += qv * w4.z; acc[ii][3] += qv * w4.w;
        }
    }
#pragma unroll
    for (int ii = 0; ii < 16; ii++) {
        float4 o; o.x = acc[ii][0]; o.y = acc[ii][1]; o.z = acc[ii][2]; o.w = acc[ii][3];
        *(float4*)&g_qW[((size_t)b * 128 + i0 + ii) * 512 + e] = o;
    }
}

// ---------------- K3pre: qk[b][i][j] = q . k  (base logits, unscaled) -------
__global__ __launch_bounds__(256) void k3pre() {
    const int b = blockIdx.x;
    __shared__ float qT[32][128];
    __shared__ float kT[32][128];
    const int t = threadIdx.x, ty = t >> 4, tx = t & 15;

    float acc[8][8];
#pragma unroll
    for (int p = 0; p < 8; p++)
#pragma unroll
        for (int q = 0; q < 8; q++) acc[p][q] = 0.f;

    for (int d0 = 0; d0 < 64; d0 += 32) {
#pragma unroll
        for (int u = 0; u < 4; u++) {
            int ii = (t >> 3) + 32 * u;
            int d4 = (t & 7) * 4;
            float4 a = *(const float4*)&g_q[((size_t)b * 128 + ii) * 64 + d0 + d4];
            qT[d4 + 0][ii] = a.x; qT[d4 + 1][ii] = a.y;
            qT[d4 + 2][ii] = a.z; qT[d4 + 3][ii] = a.w;
            float4 bb = *(const float4*)&g_k[((size_t)b * 128 + ii) * 64 + d0 + d4];
            kT[d4 + 0][ii] = bb.x; kT[d4 + 1][ii] = bb.y;
            kT[d4 + 2][ii] = bb.z; kT[d4 + 3][ii] = bb.w;
        }
        __syncthreads();
#pragma unroll
        for (int d = 0; d < 32; d++) {
            float a[8], bl[8];
            *(float4*)(a)      = *(float4*)&qT[d][ty * 8];
            *(float4*)(a + 4)  = *(float4*)&qT[d][ty * 8 + 4];
            *(float4*)(bl)     = *(float4*)&kT[d][tx * 8];
            *(float4*)(bl + 4) = *(float4*)&kT[d][tx * 8 + 4];
#pragma unroll
            for (int p = 0; p < 8; p++)
#pragma unroll
                for (int q = 0; q < 8; q++) acc[p][q] += a[p] * bl[q];
        }
        __syncthreads();
    }
#pragma unroll
    for (int p = 0; p < 8; p++) {
        float* dst = &g_aw[((size_t)b * 128 + ty * 8 + p) * 128 + tx * 8];
        *(float4*)dst       = *(float4*)&acc[p][0];
        *(float4*)(dst + 4) = *(float4*)&acc[p][4];
    }
}

// ---------------- K34: ONE-PASS logits + exp + s-accum over know ------------
// Block = (n,i). know streamed once through double-buffered 16KB smem tiles.
// qW lives in REGISTERS (per-warp e-chunk); p passed to phase3 as packed ull.
#define TJ 8
__global__ __launch_bounds__(256, 2) void k34_onepass(const float* __restrict__ know,
                                                      const int* __restrict__ mask) {
    __shared__ float kn_s[2][TJ][512];   // 32 KB (double buffer)
    __shared__ float p_s[8][128];        // 4 KB  (unnormalized p, full)
    __shared__ ull_t pT2[TJ][8];         // 512 B (packed (p,p), current tile)
    __shared__ float ptile[8][TJ];       // 256 B (logit accum, current tile)
    __shared__ float qk_s[8][128];       // 4 KB  (q.k base from k3pre)
    __shared__ unsigned char m8[8][128]; // 1 KB
    __shared__ float inv_s[8];

    const int n = blockIdx.x >> 7;
    const int i = blockIdx.x & 127;
    const int t = threadIdx.x, w = t >> 5, l = t & 31;
    const int cch = w & 3, jh = w >> 2;          // phase-1 warp role
    const int es = 128 * cch + 4 * l;            // this lane's e-slice (phase 1)
    const int g = t >> 7;                        // phase-3 h-group (0/1)
    const int e0 = (t & 127) << 2;               // phase-3 e-chunk

    // ---- preload q.k base + mask ----
    {
        int h = t >> 5, j0 = (t & 31) << 2;
        *(float4*)&qk_s[h][j0] =
            *(const float4*)&g_aw[(((size_t)(n * 8 + h) * 128 + i)) * 128 + j0];
        int4 mm = *(const int4*)&mask[(((size_t)(n * 8 + h) * 128 + i)) * 128 + j0];
        uchar4 mb;
        mb.x = (unsigned char)(mm.x != 0); mb.y = (unsigned char)(mm.y != 0);
        mb.z = (unsigned char)(mm.z != 0); mb.w = (unsigned char)(mm.w != 0);
        *(uchar4*)&m8[h][j0] = mb;
    }

    // ---- qW slice into registers: 8 heads x 4 e (2 ull each) ----
    ull_t qw[8][2];
#pragma unroll
    for (int h = 0; h < 8; h++) {
        ulonglong2 q2 = *(const ulonglong2*)
            &g_qW[(((size_t)(n * 8 + h) * 128 + i)) * 512 + es];
        qw[h][0] = q2.x; qw[h][1] = q2.y;
    }

    const float* knbase = know + ((size_t)n * 16384 + (size_t)i * 128) * 512;

    // persistent s accumulators: heads [4g,4g+4) at e-chunk e0 (e-pairs packed)
    ull_t accv[4][2];
#pragma unroll
    for (int hh = 0; hh < 4; hh++) { accv[hh][0] = 0ull; accv[hh][1] = 0ull; }

    __syncthreads();   // qk_s ready

    // ---- prologue: tile 0 into buf 0, ptile init for tile 0 ----
#pragma unroll
    for (int u = 0; u < 4; u++) {
        int c = t + 256 * u;
        float4 v = *(const float4*)(knbase + (size_t)(c >> 7) * 512 + ((c & 127) << 2));
        *(float4*)&kn_s[0][c >> 7][(c & 127) << 2] = v;
    }
    if (t < 64) ptile[t >> 3][t & 7] = qk_s[t >> 3][t & 7];

    int buf = 0;
#pragma unroll 1
    for (int tt = 0; tt < 16; tt++) {
        __syncthreads();   // tile[buf] + ptile ready

        // prefetch next tile into regs (overlaps phase 1)
        float4 pf[4];
        if (tt < 15) {
#pragma unroll
            for (int u = 0; u < 4; u++) {
                int c = t + 256 * u;
                pf[u] = *(const float4*)(knbase +
                        (size_t)((tt + 1) * TJ + (c >> 7)) * 512 + ((c & 127) << 2));
            }
        }

        // ---- phase 1: logits (qW in regs), warp (cch, jh) does 4 j rows ----
#pragma unroll
        for (int jj = 0; jj < 4; jj++) {
            const int jl = 4 * jh + jj;
            ulonglong2 kv = *(const ulonglong2*)&kn_s[buf][jl][es];
            ull_t a2[8];
#pragma unroll
            for (int h = 0; h < 8; h++) {
                a2[h] = 0ull;
                FMA2(a2[h], kv.x, qw[h][0]);
                FMA2(a2[h], kv.y, qw[h][1]);
            }
            float v[8];
#pragma unroll
            for (int h = 0; h < 8; h++) {
                float lo, hi; UNPACK2(lo, hi, a2[h]); v[h] = lo + hi;
            }
            // value-halving butterfly: 8 vals over 32 lanes
#pragma unroll
            for (int h = 0; h < 4; h++) {
                float give = (l & 16) ? v[h] : v[h + 4];
                float keep = (l & 16) ? v[h + 4] : v[h];
                v[h] = keep + __shfl_xor_sync(0xffffffffu, give, 16);
            }
#pragma unroll
            for (int h = 0; h < 2; h++) {
                float give = (l & 8) ? v[h] : v[h + 2];
                float keep = (l & 8) ? v[h + 2] : v[h];
                v[h] = keep + __shfl_xor_sync(0xffffffffu, give, 8);
            }
            {
                float give = (l & 4) ? v[0] : v[1];
                float keep = (l & 4) ? v[1] : v[0];
                v[0] = keep + __shfl_xor_sync(0xffffffffu, give, 4);
            }
            v[0] += __shfl_xor_sync(0xffffffffu, v[0], 2);
            v[0] += __shfl_xor_sync(0xffffffffu, v[0], 1);
            if ((l & 3) == 0) {
                const int h = ((l >> 4) & 1) * 4 + ((l >> 3) & 1) * 2 + ((l >> 2) & 1);
                atomicAdd(&ptile[h][jl], v[0]);
            }
        }
        __syncthreads();   // logit atomics done

        // ---- exp: 64 threads, one per (h, jl) ----
        if (t < 64) {
            const int h = t >> 3, jl = t & 7, j = tt * TJ + jl;
            float p = m8[h][j] ? __expf(ptile[h][jl] * SCALING) : 0.f;
            p_s[h][j] = p;
            ull_t p2; PACK2(p2, p, p);
            pT2[jl][h] = p2;
        }
        __syncthreads();   // p ready

        // ---- phase 3: s accumulation from same tile ----
        {
            const int h0 = g * 4;
#pragma unroll
            for (int jl = 0; jl < TJ; jl++) {
                ulonglong2 kv = *(const ulonglong2*)&kn_s[buf][jl][e0];
                ulonglong2 pa = *(const ulonglong2*)&pT2[jl][h0];
                ulonglong2 pb = *(const ulonglong2*)&pT2[jl][h0 + 2];
                FMA2(accv[0][0], pa.x, kv.x); FMA2(accv[0][1], pa.x, kv.y);
                FMA2(accv[1][0], pa.y, kv.x); FMA2(accv[1][1], pa.y, kv.y);
                FMA2(accv[2][0], pb.x, kv.x); FMA2(accv[2][1], pb.x, kv.y);
                FMA2(accv[3][0], pb.y, kv.x); FMA2(accv[3][1], pb.y, kv.y);
            }
        }

        // ---- stage next tile + next ptile init ----
        if (tt < 15) {
#pragma unroll
            for (int u = 0; u < 4; u++) {
                int c = t + 256 * u;
                *(float4*)&kn_s[buf ^ 1][c >> 7][(c & 127) << 2] = pf[u];
            }
            if (t < 64)
                ptile[t >> 3][t & 7] = qk_s[t >> 3][(tt + 1) * TJ + (t & 7)];
        }
        buf ^= 1;
    }

    // ---- normalization: warp w sums p_s over head w ----
    {
        float s = 0.f;
#pragma unroll
        for (int c = 0; c < 4; c++) s += p_s[w][l + 32 * c];
#pragma unroll
        for (int off = 16; off; off >>= 1)
            s += __shfl_xor_sync(0xffffffffu, s, off);
        if (l == 0) inv_s[w] = 1.f / s;
    }
    __syncthreads();

    // ---- write s (normalized) ----
    {
        const int h0 = g * 4;
#pragma unroll
        for (int hh = 0; hh < 4; hh++) {
            float inv = inv_s[h0 + hh];
            float4 o;
            UNPACK2(o.x, o.y, accv[hh][0]);
            UNPACK2(o.z, o.w, accv[hh][1]);
            o.x *= inv; o.y *= inv; o.z *= inv; o.w *= inv;
            *(float4*)&g_s[(((size_t)(n * 8 + h0 + hh) * 128 + i)) * 512 + e0] = o;
        }
    }
    // ---- write normalized aw ----
#pragma unroll
    for (int u = 0; u < 4; u++) {
        int c = t + 256 * u;
        int h = c >> 7, j = c & 127;
        g_aw[(((size_t)(n * 8 + h) * 128 + i)) * 128 + j] = p_s[h][j] * inv_s[h];
    }
}

// ---------------- K4b: attn = aw@v + s@Wknow_h^T  (combined K=640 GEMM) -----
__global__ __launch_bounds__(256) void k4b_attn(const float* __restrict__ Wknow) {
    __shared__ float As[16][64];
    __shared__ float Bs[16][64];
    const int h = blockIdx.y;
    const int r0 = blockIdx.x * 64;
    const int n = r0 >> 7;
    const int i0 = r0 & 127;
    const int t = threadIdx.x;
    const int ty = t >> 4, tx = t & 15;

    float acc[4][4];
#pragma unroll
    for (int a = 0; a < 4; a++)
#pragma unroll
        for (int b = 0; b < 4; b++) acc[a][b] = 0.f;

    for (int k0 = 0; k0 < 640; k0 += 16) {
        {
            const int rr = t >> 2, kq = (t & 3) * 4;
            const int ii = i0 + rr;
            float4 a4;
            if (k0 < 128)
                a4 = *(const float4*)&g_aw[((size_t)(n * 8 + h) * 128 + ii) * 128 + k0 + kq];
            else
                a4 = *(const float4*)&g_s[((size_t)(n * 8 + h) * 128 + ii) * 512 + (k0 - 128) + kq];
            As[kq + 0][rr] = a4.x; As[kq + 1][rr] = a4.y;
            As[kq + 2][rr] = a4.z; As[kq + 3][rr] = a4.w;
        }
        if (k0 < 128) {
            const int kr = t >> 4, dq = (t & 15) * 4;
            float4 b4 = *(const float4*)&g_v[((size_t)(n * 8 + h) * 128 + (k0 + kr)) * 64 + dq];
            *(float4*)&Bs[kr][dq] = b4;
        } else {
            const int d = t >> 2, eq = (t & 3) * 4;
            float4 w4 = *(const float4*)(Wknow + (size_t)(h * 64 + d) * 512 + (k0 - 128) + eq);
            Bs[eq + 0][d] = w4.x; Bs[eq + 1][d] = w4.y;
            Bs[eq + 2][d] = w4.z; Bs[eq + 3][d] = w4.w;
        }
        __syncthreads();
#pragma unroll
        for (int kk = 0; kk < 16; kk++) {
            float4 a4 = *(float4*)&As[kk][ty * 4];
            float4 b4 = *(float4*)&Bs[kk][tx * 4];
            acc[0][0] += a4.x * b4.x; acc[0][1] += a4.x * b4.y; acc[0][2] += a4.x * b4.z; acc[0][3] += a4.x * b4.w;
            acc[1][0] += a4.y * b4.x; acc[1][1] += a4.y * b4.y; acc[1][2] += a4.y * b4.z; acc[1][3] += a4.y * b4.w;
            acc[2][0] += a4.z * b4.x; acc[2][1] += a4.z * b4.y; acc[2][2] += a4.z * b4.z; acc[2][3] += a4.z * b4.w;
            acc[3][0] += a4.w * b4.x; acc[3][1] += a4.w * b4.y; acc[3][2] += a4.w * b4.z; acc[3][3] += a4.w * b4.w;
        }
        __syncthreads();
    }
#pragma unroll
    for (int ry = 0; ry < 4; ry++) {
        const int ii = i0 + ty * 4 + ry;
        float* dst = g_attn + ((size_t)ii * 16 + n) * 512 + h * 64 + tx * 4;
        *(float4*)dst = *(float4*)&acc[ry][0];
    }
}

// ---------------- K5: gating  out = g*r + (1-g)*attn ------------------------
__global__ __launch_bounds__(128) void k5_gate(const float* __restrict__ Wbeta,
                                               float* __restrict__ out) {
    const int m = blockIdx.x;
    const int t = threadIdx.x;
    const int w = t >> 5, l = t & 31;
    __shared__ float red[4];

    const float* a = g_attn + (size_t)m * 512;
    const float* r = g_r + (size_t)m * 512;

    float z = 0.f;
#pragma unroll
    for (int c = 0; c < 4; c++) {
        int e = t + 128 * c;
        float av = a[e], rv = r[e];
        z += Wbeta[e] * av + Wbeta[512 + e] * rv + Wbeta[1024 + e] * (av - rv);
    }
#pragma unroll
    for (int off = 16; off; off >>= 1)
        z += __shfl_xor_sync(0xffffffffu, z, off);
    if (l == 0) red[w] = z;
    __syncthreads();
    float zt = red[0] + red[1] + red[2] + red[3];
    float g = 1.f / (1.f + __expf(-zt));

#pragma unroll
    for (int c = 0; c < 4; c++) {
        int e = t + 128 * c;
        out[(size_t)m * 512 + e] = g * r[e] + (1.f - g) * a[e];
    }
}

// ---------------- launch -----------------------------------------------------
extern "C" void kernel_launch(void* const* d_in, const int* in_sizes, int n_in,
                              void* d_out, int out_size) {
    const float* x     = (const float*)d_in[0];
    const float* know  = (const float*)d_in[1];
    const int*   mask  = (const int*)d_in[2];
    const float* Wq    = (const float*)d_in[3];
    const float* Wk    = (const float*)d_in[4];
    const float* Wv    = (const float*)d_in[5];
    const float* Wknow = (const float*)d_in[6];
    const float* Wskip = (const float*)d_in[7];
    const float* Wbeta = (const float*)d_in[8];
    float* out = (float*)d_out;

    k1_proj<<<dim3(16, 16), 256>>>(x, Wq, Wk, Wv, Wskip);
    k2_qw<<<dim3(128, 8), 128>>>(Wknow);
    k3pre<<<128, 256>>>();
    k34_onepass<<<2048, 256>>>(know, mask);
    k4b_attn<<<dim3(32, 8), 256>>>(Wknow);
    k5_gate<<<2048, 128>>>(Wbeta, out);
}

// round 6
// speedup vs baseline: 1.5809x; 1.1125x over previous
#include <cuda_runtime.h>
#include <cstdint>

#define SLEN 128
#define BSZ  16
#define EMB  512
#define NHEAD 8
#define HDIM 64
#define BH   (BSZ*NHEAD)   // 128
#define NEG_INF (-1e9f)
#define SCALING 0.125f     // 1/sqrt(64)

// ---- f32x2 packed math (Blackwell) ----
#define FMA2(d, a, b) asm("fma.rn.f32x2 %0, %1, %2, %0;" : "+l"(d) : "l"(a), "l"(b))
#define PACK2(u, lo, hi) asm("mov.b64 %0, {%1, %2};" : "=l"(u) : "f"(lo), "f"(hi))
#define UNPACK2(lo, hi, u) asm("mov.b64 {%0, %1}, %2;" : "=f"(lo), "=f"(hi) : "l"(u))

typedef unsigned long long ull_t;

__device__ __forceinline__ void cpa16(uint32_t saddr, const void* gaddr) {
    asm volatile("cp.async.ca.shared.global [%0], [%1], 16;" :: "r"(saddr), "l"(gaddr));
}
__device__ __forceinline__ void cpa_commit() {
    asm volatile("cp.async.commit_group;");
}
__device__ __forceinline__ void cpa_wait_all() {
    asm volatile("cp.async.wait_group 0;");
}

// ---------------- scratch (device globals; no runtime alloc) ----------------
__device__ float g_q[BH*SLEN*HDIM];        // [b][i][d]
__device__ float g_k[BH*SLEN*HDIM];        // [b][j][d]
__device__ float g_v[BH*SLEN*HDIM];        // [b][j][d]
__device__ float g_r[SLEN*BSZ*EMB];        // [m][e]
__device__ float g_qW[BH*SLEN*EMB];        // [b][i][e]
__device__ float g_aw[BH*SLEN*SLEN];       // [b][i][j]  (qk base, then normalized aw)
__device__ float g_s[BH*SLEN*EMB];         // [b][i][e]
__device__ float g_attn[SLEN*BSZ*EMB];     // [m][e]

// ---------------- K1: fused projections  C = X(2048x512) @ W^T --------------
__global__ __launch_bounds__(256) void k1_proj(const float* __restrict__ x,
                                               const float* __restrict__ Wq,
                                               const float* __restrict__ Wk,
                                               const float* __restrict__ Wv,
                                               const float* __restrict__ Wskip) {
    __shared__ float As[16][128];
    __shared__ float Bs[16][128];
    const int m0 = blockIdx.y * 128;
    const int c0 = blockIdx.x * 128;
    const int sel = c0 >> 9;
    const float* W = (sel == 0) ? Wq : (sel == 1) ? Wk : (sel == 2) ? Wv : Wskip;
    const int e0 = c0 & 511;

    const int t  = threadIdx.x;
    const int ty = t >> 4, tx = t & 15;
    const int lr = t >> 1;
    const int lc = (t & 1) * 8;

    ull_t acc2[8][4];
#pragma unroll
    for (int a = 0; a < 8; a++)
#pragma unroll
        for (int b = 0; b < 4; b++) acc2[a][b] = 0ull;

    for (int k0 = 0; k0 < 512; k0 += 16) {
        float4 a0 = *(const float4*)(x + (size_t)(m0 + lr) * 512 + k0 + lc);
        float4 a1 = *(const float4*)(x + (size_t)(m0 + lr) * 512 + k0 + lc + 4);
        float4 b0 = *(const float4*)(W + (size_t)(e0 + lr) * 512 + k0 + lc);
        float4 b1 = *(const float4*)(W + (size_t)(e0 + lr) * 512 + k0 + lc + 4);
        As[lc + 0][lr] = a0.x; As[lc + 1][lr] = a0.y;
        As[lc + 2][lr] = a0.z; As[lc + 3][lr] = a0.w;
        As[lc + 4][lr] = a1.x; As[lc + 5][lr] = a1.y;
        As[lc + 6][lr] = a1.z; As[lc + 7][lr] = a1.w;
        Bs[lc + 0][lr] = b0.x; Bs[lc + 1][lr] = b0.y;
        Bs[lc + 2][lr] = b0.z; Bs[lc + 3][lr] = b0.w;
        Bs[lc + 4][lr] = b1.x; Bs[lc + 5][lr] = b1.y;
        Bs[lc + 6][lr] = b1.z; Bs[lc + 7][lr] = b1.w;
        __syncthreads();
#pragma unroll
        for (int kk = 0; kk < 16; kk++) {
            float a[8];
            *(float4*)(a)     = *(float4*)&As[kk][ty * 8];
            *(float4*)(a + 4) = *(float4*)&As[kk][ty * 8 + 4];
            ulonglong2 bA = *(ulonglong2*)&Bs[kk][tx * 8];
            ulonglong2 bB = *(ulonglong2*)&Bs[kk][tx * 8 + 4];
#pragma unroll
            for (int p = 0; p < 8; p++) {
                ull_t ap; PACK2(ap, a[p], a[p]);
                FMA2(acc2[p][0], ap, bA.x);
                FMA2(acc2[p][1], ap, bA.y);
                FMA2(acc2[p][2], ap, bB.x);
                FMA2(acc2[p][3], ap, bB.y);
            }
        }
        __syncthreads();
    }

    const int ecol = e0 + tx * 8;
    const int h = ecol >> 6;
    const int d0 = ecol & 63;
#pragma unroll
    for (int ry = 0; ry < 8; ry++) {
        const int m = m0 + ty * 8 + ry;
        const int i = m >> 4, n = m & 15;
        float o[8];
#pragma unroll
        for (int q = 0; q < 4; q++) UNPACK2(o[2*q], o[2*q+1], acc2[ry][q]);
        if (sel == 3) {
            float* dst = g_r + (size_t)m * 512 + ecol;
            *(float4*)dst       = *(float4*)&o[0];
            *(float4*)(dst + 4) = *(float4*)&o[4];
        } else {
            float* base = (sel == 0) ? g_q : (sel == 1) ? g_k : g_v;
            float* dst = base + ((size_t)(n * 8 + h) * 128 + i) * 64 + d0;
            *(float4*)dst       = *(float4*)&o[0];
            *(float4*)(dst + 4) = *(float4*)&o[4];
        }
    }
}

// ---------------- K2: qW = q @ Wknow_h  (per-head 2048x512x64 GEMM) ---------
// grid: (etile(4) * mtile(16), h(8)).  BM=128, BN=128, BK=16.
__global__ __launch_bounds__(256) void k2_qw(const float* __restrict__ Wknow) {
    __shared__ float As[16][128];
    __shared__ float Bs[16][128];
    const int h = blockIdx.y;
    const int m0 = (blockIdx.x & 15) * 128;
    const int e0t = (blockIdx.x >> 4) * 128;

    const int t  = threadIdx.x;
    const int ty = t >> 4, tx = t & 15;
    const int lr = t >> 1;
    const int lc = (t & 1) * 8;
    const int dr = t >> 4;          // 0..15  (B row within k-step)
    const int ec = (t & 15) * 8;    // B col chunk

    ull_t acc2[8][4];
#pragma unroll
    for (int a = 0; a < 8; a++)
#pragma unroll
        for (int b = 0; b < 4; b++) acc2[a][b] = 0ull;

    for (int k0 = 0; k0 < 64; k0 += 16) {
        // A tile: rows m0+lr, d = k0+lc..+7 from g_q (head h)
        {
            const int m = m0 + lr;
            const int n = m >> 7, i = m & 127;
            const float* ar = &g_q[((size_t)(n * 8 + h) * 128 + i) * 64 + k0 + lc];
            float4 a0 = *(const float4*)ar;
            float4 a1 = *(const float4*)(ar + 4);
            As[lc + 0][lr] = a0.x; As[lc + 1][lr] = a0.y;
            As[lc + 2][lr] = a0.z; As[lc + 3][lr] = a0.w;
            As[lc + 4][lr] = a1.x; As[lc + 5][lr] = a1.y;
            As[lc + 6][lr] = a1.z; As[lc + 7][lr] = a1.w;
        }
        // B tile: Wknow row (h*64+k0+dr), cols e0t+ec..+7
        {
            const float* br = Wknow + (size_t)(h * 64 + k0 + dr) * 512 + e0t + ec;
            float4 b0 = *(const float4*)br;
            float4 b1 = *(const float4*)(br + 4);
            *(float4*)&Bs[dr][ec]     = b0;
            *(float4*)&Bs[dr][ec + 4] = b1;
        }
        __syncthreads();
#pragma unroll
        for (int kk = 0; kk < 16; kk++) {
            float a[8];
            *(float4*)(a)     = *(float4*)&As[kk][ty * 8];
            *(float4*)(a + 4) = *(float4*)&As[kk][ty * 8 + 4];
            ulonglong2 bA = *(ulonglong2*)&Bs[kk][tx * 8];
            ulonglong2 bB = *(ulonglong2*)&Bs[kk][tx * 8 + 4];
#pragma unroll
            for (int p = 0; p < 8; p++) {
                ull_t ap; PACK2(ap, a[p], a[p]);
                FMA2(acc2[p][0], ap, bA.x);
                FMA2(acc2[p][1], ap, bA.y);
                FMA2(acc2[p][2], ap, bB.x);
                FMA2(acc2[p][3], ap, bB.y);
            }
        }
        __syncthreads();
    }

#pragma unroll
    for (int ry = 0; ry < 8; ry++) {
        const int m = m0 + ty * 8 + ry;
        const int n = m >> 7, i = m & 127;
        float o[8];
#pragma unroll
        for (int q = 0; q < 4; q++) UNPACK2(o[2*q], o[2*q+1], acc2[ry][q]);
        float* dst = &g_qW[((size_t)(n * 8 + h) * 128 + i) * 512 + e0t + tx * 8];
        *(float4*)dst       = *(float4*)&o[0];
        *(float4*)(dst + 4) = *(float4*)&o[4];
    }
}

// ---------------- K3pre: qk[b][i][j] = q . k  (base logits, unscaled) -------
__global__ __launch_bounds__(256) void k3pre() {
    const int b = blockIdx.x;
    __shared__ float qT[32][128];
    __shared__ float kT[32][128];
    const int t = threadIdx.x, ty = t >> 4, tx = t & 15;

    float acc[8][8];
#pragma unroll
    for (int p = 0; p < 8; p++)
#pragma unroll
        for (int q = 0; q < 8; q++) acc[p][q] = 0.f;

    for (int d0 = 0; d0 < 64; d0 += 32) {
#pragma unroll
        for (int u = 0; u < 4; u++) {
            int ii = (t >> 3) + 32 * u;
            int d4 = (t & 7) * 4;
            float4 a = *(const float4*)&g_q[((size_t)b * 128 + ii) * 64 + d0 + d4];
            qT[d4 + 0][ii] = a.x; qT[d4 + 1][ii] = a.y;
            qT[d4 + 2][ii] = a.z; qT[d4 + 3][ii] = a.w;
            float4 bb = *(const float4*)&g_k[((size_t)b * 128 + ii) * 64 + d0 + d4];
            kT[d4 + 0][ii] = bb.x; kT[d4 + 1][ii] = bb.y;
            kT[d4 + 2][ii] = bb.z; kT[d4 + 3][ii] = bb.w;
        }
        __syncthreads();
#pragma unroll
        for (int d = 0; d < 32; d++) {
            float a[8], bl[8];
            *(float4*)(a)      = *(float4*)&qT[d][ty * 8];
            *(float4*)(a + 4)  = *(float4*)&qT[d][ty * 8 + 4];
            *(float4*)(bl)     = *(float4*)&kT[d][tx * 8];
            *(float4*)(bl + 4) = *(float4*)&kT[d][tx * 8 + 4];
#pragma unroll
            for (int p = 0; p < 8; p++)
#pragma unroll
                for (int q = 0; q < 8; q++) acc[p][q] += a[p] * bl[q];
        }
        __syncthreads();
    }
#pragma unroll
    for (int p = 0; p < 8; p++) {
        float* dst = &g_aw[((size_t)b * 128 + ty * 8 + p) * 128 + tx * 8];
        *(float4*)dst       = *(float4*)&acc[p][0];
        *(float4*)(dst + 4) = *(float4*)&acc[p][4];
    }
}

// ---------------- K34: ONE-PASS logits + exp + s-accum over know ------------
// TJ=16 j-rows per tile (32KB), double-buffered via cp.async.
// Phase1: warp (cch, jh) -> partial logits via butterfly, STS (no atomics).
// Exp stage: 128 threads combine 4 partials + qk base, mask, expf.
// Phase3: all 256 threads accumulate s from same smem tile.
#define TJ 16
__global__ __launch_bounds__(256, 2) void k34_onepass(const float* __restrict__ know,
                                                      const int* __restrict__ mask) {
    __shared__ float kn_s[2][TJ][512];   // 64 KB (double buffer)
    __shared__ float part_s[4][TJ][8];   // 2 KB  (per-warp logit partials)
    __shared__ ull_t pT2[TJ][8];         // 1 KB  (packed (p,p))
    __shared__ float p_s[8][128];        // 4 KB  (unnormalized p, full)
    __shared__ float qk_s[8][128];       // 4 KB  (q.k base from k3pre)
    __shared__ unsigned char m8[8][128]; // 1 KB
    __shared__ float inv_s[8];

    const int n = blockIdx.x >> 7;
    const int i = blockIdx.x & 127;
    const int t = threadIdx.x, w = t >> 5, l = t & 31;
    const int cch = w & 3, jh = w >> 2;          // phase-1 warp role
    const int es = 128 * cch + 4 * l;            // this lane's e-slice (phase 1)
    const int g = t >> 7;                        // phase-3 h-group (0/1)
    const int e0 = (t & 127) << 2;               // phase-3 e-chunk

    // ---- preload q.k base + mask ----
    {
        int h = t >> 5, j0 = (t & 31) << 2;
        *(float4*)&qk_s[h][j0] =
            *(const float4*)&g_aw[(((size_t)(n * 8 + h) * 128 + i)) * 128 + j0];
        int4 mm = *(const int4*)&mask[(((size_t)(n * 8 + h) * 128 + i)) * 128 + j0];
        uchar4 mb;
        mb.x = (unsigned char)(mm.x != 0); mb.y = (unsigned char)(mm.y != 0);
        mb.z = (unsigned char)(mm.z != 0); mb.w = (unsigned char)(mm.w != 0);
        *(uchar4*)&m8[h][j0] = mb;
    }

    // ---- qW slice into registers: 8 heads x 4 e (2 ull each) ----
    ull_t qw[8][2];
#pragma unroll
    for (int h = 0; h < 8; h++) {
        ulonglong2 q2 = *(const ulonglong2*)
            &g_qW[(((size_t)(n * 8 + h) * 128 + i)) * 512 + es];
        qw[h][0] = q2.x; qw[h][1] = q2.y;
    }

    const float* knbase = know + ((size_t)n * 16384 + (size_t)i * 128) * 512;
    const uint32_t kn_sa = (uint32_t)__cvta_generic_to_shared(&kn_s[0][0][0]);

    // persistent s accumulators: heads [4g,4g+4) at e-chunk e0 (e-pairs packed)
    ull_t accv[4][2];
#pragma unroll
    for (int hh = 0; hh < 4; hh++) { accv[hh][0] = 0ull; accv[hh][1] = 0ull; }

    // ---- prologue: stage tile 0 into buf 0 via cp.async ----
#pragma unroll
    for (int u = 0; u < 8; u++) {
        int c = t + 256 * u;                 // 0..2047 -> (row, 16B chunk)
        int r = c >> 7, ch = c & 127;
        cpa16(kn_sa + (uint32_t)(r * 2048 + ch * 16),
              knbase + (size_t)r * 512 + ch * 4);
    }
    cpa_commit();

    int buf = 0;
#pragma unroll 1
    for (int tt = 0; tt < 8; tt++) {
        cpa_wait_all();
        __syncthreads();   // tile[buf] visible to all

        // stage next tile into buf^1 (overlaps all compute below)
        if (tt < 7) {
            const float* nb = knbase + (size_t)(tt + 1) * TJ * 512;
            const uint32_t sb = kn_sa + (uint32_t)((buf ^ 1) * TJ * 2048);
#pragma unroll
            for (int u = 0; u < 8; u++) {
                int c = t + 256 * u;
                int r = c >> 7, ch = c & 127;
                cpa16(sb + (uint32_t)(r * 2048 + ch * 16),
                      nb + (size_t)r * 512 + ch * 4);
            }
            cpa_commit();
        }

        // ---- phase 1: partial logits; warp (cch, jh) does 8 j rows ----
#pragma unroll
        for (int jj = 0; jj < 8; jj++) {
            const int jl = 8 * jh + jj;
            ulonglong2 kv = *(const ulonglong2*)&kn_s[buf][jl][es];
            ull_t a2[8];
#pragma unroll
            for (int h = 0; h < 8; h++) {
                a2[h] = 0ull;
                FMA2(a2[h], kv.x, qw[h][0]);
                FMA2(a2[h], kv.y, qw[h][1]);
            }
            float v[8];
#pragma unroll
            for (int h = 0; h < 8; h++) {
                float lo, hi; UNPACK2(lo, hi, a2[h]); v[h] = lo + hi;
            }
            // value-halving butterfly: 8 vals over 32 lanes
#pragma unroll
            for (int h = 0; h < 4; h++) {
                float give = (l & 16) ? v[h] : v[h + 4];
                float keep = (l & 16) ? v[h + 4] : v[h];
                v[h] = keep + __shfl_xor_sync(0xffffffffu, give, 16);
            }
#pragma unroll
            for (int h = 0; h < 2; h++) {
                float give = (l & 8) ? v[h] : v[h + 2];
                float keep = (l & 8) ? v[h + 2] : v[h];
                v[h] = keep + __shfl_xor_sync(0xffffffffu, give, 8);
            }
            {
                float give = (l & 4) ? v[0] : v[1];
                float keep = (l & 4) ? v[1] : v[0];
                v[0] = keep + __shfl_xor_sync(0xffffffffu, give, 4);
            }
            v[0] += __shfl_xor_sync(0xffffffffu, v[0], 2);
            v[0] += __shfl_xor_sync(0xffffffffu, v[0], 1);
            if ((l & 3) == 0) {
                const int h = ((l >> 4) & 1) * 4 + ((l >> 3) & 1) * 2 + ((l >> 2) & 1);
                part_s[cch][jl][h] = v[0];
            }
        }
        __syncthreads();   // partials ready

        // ---- exp: 128 threads, one per (h, jl) ----
        if (t < 128) {
            const int h = t >> 4, jl = t & 15, j = tt * TJ + jl;
            float sum = part_s[0][jl][h] + part_s[1][jl][h]
                      + part_s[2][jl][h] + part_s[3][jl][h];
            float lg = (sum + qk_s[h][j]) * SCALING;
            float p = m8[h][j] ? __expf(lg) : 0.f;
            p_s[h][j] = p;
            ull_t p2; PACK2(p2, p, p);
            pT2[jl][h] = p2;
        }
        __syncthreads();   // p ready

        // ---- phase 3: s accumulation from same tile ----
        {
            const int h0 = g * 4;
#pragma unroll
            for (int jl = 0; jl < TJ; jl++) {
                ulonglong2 kv = *(const ulonglong2*)&kn_s[buf][jl][e0];
                ulonglong2 pa = *(const ulonglong2*)&pT2[jl][h0];
                ulonglong2 pb = *(const ulonglong2*)&pT2[jl][h0 + 2];
                FMA2(accv[0][0], pa.x, kv.x); FMA2(accv[0][1], pa.x, kv.y);
                FMA2(accv[1][0], pa.y, kv.x); FMA2(accv[1][1], pa.y, kv.y);
                FMA2(accv[2][0], pb.x, kv.x); FMA2(accv[2][1], pb.x, kv.y);
                FMA2(accv[3][0], pb.y, kv.x); FMA2(accv[3][1], pb.y, kv.y);
            }
        }
        buf ^= 1;
    }

    // ---- normalization: warp w sums p_s over head w ----
    {
        float s = 0.f;
#pragma unroll
        for (int c = 0; c < 4; c++) s += p_s[w][l + 32 * c];
#pragma unroll
        for (int off = 16; off; off >>= 1)
            s += __shfl_xor_sync(0xffffffffu, s, off);
        if (l == 0) inv_s[w] = 1.f / s;
    }
    __syncthreads();

    // ---- write s (normalized) ----
    {
        const int h0 = g * 4;
#pragma unroll
        for (int hh = 0; hh < 4; hh++) {
            float inv = inv_s[h0 + hh];
            float4 o;
            UNPACK2(o.x, o.y, accv[hh][0]);
            UNPACK2(o.z, o.w, accv[hh][1]);
            o.x *= inv; o.y *= inv; o.z *= inv; o.w *= inv;
            *(float4*)&g_s[(((size_t)(n * 8 + h0 + hh) * 128 + i)) * 512 + e0] = o;
        }
    }
    // ---- write normalized aw ----
#pragma unroll
    for (int u = 0; u < 4; u++) {
        int c = t + 256 * u;
        int h = c >> 7, j = c & 127;
        g_aw[(((size_t)(n * 8 + h) * 128 + i)) * 128 + j] = p_s[h][j] * inv_s[h];
    }
}

// ---------------- K4b: attn = aw@v + s@Wknow_h^T  (combined K=640 GEMM) -----
__global__ __launch_bounds__(256) void k4b_attn(const float* __restrict__ Wknow) {
    __shared__ float As[16][64];
    __shared__ float Bs[16][64];
    const int h = blockIdx.y;
    const int r0 = blockIdx.x * 64;
    const int n = r0 >> 7;
    const int i0 = r0 & 127;
    const int t = threadIdx.x;
    const int ty = t >> 4, tx = t & 15;

    ull_t acc2[4][2];
#pragma unroll
    for (int a = 0; a < 4; a++) { acc2[a][0] = 0ull; acc2[a][1] = 0ull; }

    for (int k0 = 0; k0 < 640; k0 += 16) {
        {
            const int rr = t >> 2, kq = (t & 3) * 4;
            const int ii = i0 + rr;
            float4 a4;
            if (k0 < 128)
                a4 = *(const float4*)&g_aw[((size_t)(n * 8 + h) * 128 + ii) * 128 + k0 + kq];
            else
                a4 = *(const float4*)&g_s[((size_t)(n * 8 + h) * 128 + ii) * 512 + (k0 - 128) + kq];
            As[kq + 0][rr] = a4.x; As[kq + 1][rr] = a4.y;
            As[kq + 2][rr] = a4.z; As[kq + 3][rr] = a4.w;
        }
        if (k0 < 128) {
            const int kr = t >> 4, dq = (t & 15) * 4;
            float4 b4 = *(const float4*)&g_v[((size_t)(n * 8 + h) * 128 + (k0 + kr)) * 64 + dq];
            *(float4*)&Bs[kr][dq] = b4;
        } else {
            const int d = t >> 2, eq = (t & 3) * 4;
            float4 w4 = *(const float4*)(Wknow + (size_t)(h * 64 + d) * 512 + (k0 - 128) + eq);
            Bs[eq + 0][d] = w4.x; Bs[eq + 1][d] = w4.y;
            Bs[eq + 2][d] = w4.z; Bs[eq + 3][d] = w4.w;
        }
        __syncthreads();
#pragma unroll
        for (int kk = 0; kk < 16; kk++) {
            float4 a4 = *(float4*)&As[kk][ty * 4];
            ulonglong2 b2 = *(ulonglong2*)&Bs[kk][tx * 4];
            ull_t ap;
            PACK2(ap, a4.x, a4.x); FMA2(acc2[0][0], ap, b2.x); FMA2(acc2[0][1], ap, b2.y);
            PACK2(ap, a4.y, a4.y); FMA2(acc2[1][0], ap, b2.x); FMA2(acc2[1][1], ap, b2.y);
            PACK2(ap, a4.z, a4.z); FMA2(acc2[2][0], ap, b2.x); FMA2(acc2[2][1], ap, b2.y);
            PACK2(ap, a4.w, a4.w); FMA2(acc2[3][0], ap, b2.x); FMA2(acc2[3][1], ap, b2.y);
        }
        __syncthreads();
    }
#pragma unroll
    for (int ry = 0; ry < 4; ry++) {
        const int ii = i0 + ty * 4 + ry;
        float4 o;
        UNPACK2(o.x, o.y, acc2[ry][0]);
        UNPACK2(o.z, o.w, acc2[ry][1]);
        float* dst = g_attn + ((size_t)ii * 16 + n) * 512 + h * 64 + tx * 4;
        *(float4*)dst = o;
    }
}

// ---------------- K5: gating  out = g*r + (1-g)*attn ------------------------
__global__ __launch_bounds__(128) void k5_gate(const float* __restrict__ Wbeta,
                                               float* __restrict__ out) {
    const int m = blockIdx.x;
    const int t = threadIdx.x;
    const int w = t >> 5, l = t & 31;
    __shared__ float red[4];

    const float* a = g_attn + (size_t)m * 512;
    const float* r = g_r + (size_t)m * 512;

    float z = 0.f;
#pragma unroll
    for (int c = 0; c < 4; c++) {
        int e = t + 128 * c;
        float av = a[e], rv = r[e];
        z += Wbeta[e] * av + Wbeta[512 + e] * rv + Wbeta[1024 + e] * (av - rv);
    }
#pragma unroll
    for (int off = 16; off; off >>= 1)
        z += __shfl_xor_sync(0xffffffffu, z, off);
    if (l == 0) red[w] = z;
    __syncthreads();
    float zt = red[0] + red[1] + red[2] + red[3];
    float g = 1.f / (1.f + __expf(-zt));

#pragma unroll
    for (int c = 0; c < 4; c++) {
        int e = t + 128 * c;
        out[(size_t)m * 512 + e] = g * r[e] + (1.f - g) * a[e];
    }
}

// ---------------- launch -----------------------------------------------------
extern "C" void kernel_launch(void* const* d_in, const int* in_sizes, int n_in,
                              void* d_out, int out_size) {
    const float* x     = (const float*)d_in[0];
    const float* know  = (const float*)d_in[1];
    const int*   mask  = (const int*)d_in[2];
    const float* Wq    = (const float*)d_in[3];
    const float* Wk    = (const float*)d_in[4];
    const float* Wv    = (const float*)d_in[5];
    const float* Wknow = (const float*)d_in[6];
    const float* Wskip = (const float*)d_in[7];
    const float* Wbeta = (const float*)d_in[8];
    float* out = (float*)d_out;

    k1_proj<<<dim3(16, 16), 256>>>(x, Wq, Wk, Wv, Wskip);
    k2_qw<<<dim3(64, 8), 256>>>(Wknow);
    k3pre<<<128, 256>>>();
    k34_onepass<<<2048, 256>>>(know, mask);
    k4b_attn<<<dim3(32, 8), 256>>>(Wknow);
    k5_gate<<<2048, 128>>>(Wbeta, out);
}

// round 7
// speedup vs baseline: 1.6130x; 1.0203x over previous
#include <cuda_runtime.h>
#include <cstdint>

#define SLEN 128
#define BSZ  16
#define EMB  512
#define NHEAD 8
#define HDIM 64
#define BH   (BSZ*NHEAD)   // 128
#define NEG_INF (-1e9f)
#define SCALING 0.125f     // 1/sqrt(64)

// ---- f32x2 packed math (Blackwell) ----
#define FMA2(d, a, b) asm("fma.rn.f32x2 %0, %1, %2, %0;" : "+l"(d) : "l"(a), "l"(b))
#define PACK2(u, lo, hi) asm("mov.b64 %0, {%1, %2};" : "=l"(u) : "f"(lo), "f"(hi))
#define UNPACK2(lo, hi, u) asm("mov.b64 {%0, %1}, %2;" : "=f"(lo), "=f"(hi) : "l"(u))

typedef unsigned long long ull_t;

__device__ __forceinline__ void cpa16(uint32_t saddr, const void* gaddr) {
    asm volatile("cp.async.ca.shared.global [%0], [%1], 16;" :: "r"(saddr), "l"(gaddr));
}
__device__ __forceinline__ void cpa_commit() {
    asm volatile("cp.async.commit_group;");
}
__device__ __forceinline__ void cpa_wait_all() {
    asm volatile("cp.async.wait_group 0;");
}

// ---------------- scratch (device globals; no runtime alloc) ----------------
__device__ float g_q[BH*SLEN*HDIM];        // [b][i][d]
__device__ float g_k[BH*SLEN*HDIM];        // [b][j][d]
__device__ float g_v[BH*SLEN*HDIM];        // [b][j][d]
__device__ float g_r[SLEN*BSZ*EMB];        // [m][e]
__device__ float g_qW[BH*SLEN*EMB];        // [b][i][e]
__device__ float g_aw[BH*SLEN*SLEN];       // [b][i][j]  (qk base, then normalized aw)
__device__ float g_s[BH*SLEN*EMB];         // [b][i][e]
__device__ float g_attn[SLEN*BSZ*EMB];     // [m][e]

// ---------------- K1: fused projections  C = X(2048x512) @ W^T --------------
__global__ __launch_bounds__(256) void k1_proj(const float* __restrict__ x,
                                               const float* __restrict__ Wq,
                                               const float* __restrict__ Wk,
                                               const float* __restrict__ Wv,
                                               const float* __restrict__ Wskip) {
    __shared__ float As[16][128];
    __shared__ float Bs[16][128];
    const int m0 = blockIdx.y * 128;
    const int c0 = blockIdx.x * 128;
    const int sel = c0 >> 9;
    const float* W = (sel == 0) ? Wq : (sel == 1) ? Wk : (sel == 2) ? Wv : Wskip;
    const int e0 = c0 & 511;

    const int t  = threadIdx.x;
    const int ty = t >> 4, tx = t & 15;
    const int lr = t >> 1;
    const int lc = (t & 1) * 8;

    ull_t acc2[8][4];
#pragma unroll
    for (int a = 0; a < 8; a++)
#pragma unroll
        for (int b = 0; b < 4; b++) acc2[a][b] = 0ull;

    for (int k0 = 0; k0 < 512; k0 += 16) {
        float4 a0 = *(const float4*)(x + (size_t)(m0 + lr) * 512 + k0 + lc);
        float4 a1 = *(const float4*)(x + (size_t)(m0 + lr) * 512 + k0 + lc + 4);
        float4 b0 = *(const float4*)(W + (size_t)(e0 + lr) * 512 + k0 + lc);
        float4 b1 = *(const float4*)(W + (size_t)(e0 + lr) * 512 + k0 + lc + 4);
        As[lc + 0][lr] = a0.x; As[lc + 1][lr] = a0.y;
        As[lc + 2][lr] = a0.z; As[lc + 3][lr] = a0.w;
        As[lc + 4][lr] = a1.x; As[lc + 5][lr] = a1.y;
        As[lc + 6][lr] = a1.z; As[lc + 7][lr] = a1.w;
        Bs[lc + 0][lr] = b0.x; Bs[lc + 1][lr] = b0.y;
        Bs[lc + 2][lr] = b0.z; Bs[lc + 3][lr] = b0.w;
        Bs[lc + 4][lr] = b1.x; Bs[lc + 5][lr] = b1.y;
        Bs[lc + 6][lr] = b1.z; Bs[lc + 7][lr] = b1.w;
        __syncthreads();
#pragma unroll
        for (int kk = 0; kk < 16; kk++) {
            float a[8];
            *(float4*)(a)     = *(float4*)&As[kk][ty * 8];
            *(float4*)(a + 4) = *(float4*)&As[kk][ty * 8 + 4];
            ulonglong2 bA = *(ulonglong2*)&Bs[kk][tx * 8];
            ulonglong2 bB = *(ulonglong2*)&Bs[kk][tx * 8 + 4];
#pragma unroll
            for (int p = 0; p < 8; p++) {
                ull_t ap; PACK2(ap, a[p], a[p]);
                FMA2(acc2[p][0], ap, bA.x);
                FMA2(acc2[p][1], ap, bA.y);
                FMA2(acc2[p][2], ap, bB.x);
                FMA2(acc2[p][3], ap, bB.y);
            }
        }
        __syncthreads();
    }

    const int ecol = e0 + tx * 8;
    const int h = ecol >> 6;
    const int d0 = ecol & 63;
#pragma unroll
    for (int ry = 0; ry < 8; ry++) {
        const int m = m0 + ty * 8 + ry;
        const int i = m >> 4, n = m & 15;
        float o[8];
#pragma unroll
        for (int q = 0; q < 4; q++) UNPACK2(o[2*q], o[2*q+1], acc2[ry][q]);
        if (sel == 3) {
            float* dst = g_r + (size_t)m * 512 + ecol;
            *(float4*)dst       = *(float4*)&o[0];
            *(float4*)(dst + 4) = *(float4*)&o[4];
        } else {
            float* base = (sel == 0) ? g_q : (sel == 1) ? g_k : g_v;
            float* dst = base + ((size_t)(n * 8 + h) * 128 + i) * 64 + d0;
            *(float4*)dst       = *(float4*)&o[0];
            *(float4*)(dst + 4) = *(float4*)&o[4];
        }
    }
}

// ---------------- K2: qW = q @ Wknow_h  (per-head 2048x512x64 GEMM) ---------
__global__ __launch_bounds__(256) void k2_qw(const float* __restrict__ Wknow) {
    __shared__ float As[16][128];
    __shared__ float Bs[16][128];
    const int h = blockIdx.y;
    const int m0 = (blockIdx.x & 15) * 128;
    const int e0t = (blockIdx.x >> 4) * 128;

    const int t  = threadIdx.x;
    const int ty = t >> 4, tx = t & 15;
    const int lr = t >> 1;
    const int lc = (t & 1) * 8;
    const int dr = t >> 4;
    const int ec = (t & 15) * 8;

    ull_t acc2[8][4];
#pragma unroll
    for (int a = 0; a < 8; a++)
#pragma unroll
        for (int b = 0; b < 4; b++) acc2[a][b] = 0ull;

    for (int k0 = 0; k0 < 64; k0 += 16) {
        {
            const int m = m0 + lr;
            const int n = m >> 7, i = m & 127;
            const float* ar = &g_q[((size_t)(n * 8 + h) * 128 + i) * 64 + k0 + lc];
            float4 a0 = *(const float4*)ar;
            float4 a1 = *(const float4*)(ar + 4);
            As[lc + 0][lr] = a0.x; As[lc + 1][lr] = a0.y;
            As[lc + 2][lr] = a0.z; As[lc + 3][lr] = a0.w;
            As[lc + 4][lr] = a1.x; As[lc + 5][lr] = a1.y;
            As[lc + 6][lr] = a1.z; As[lc + 7][lr] = a1.w;
        }
        {
            const float* br = Wknow + (size_t)(h * 64 + k0 + dr) * 512 + e0t + ec;
            float4 b0 = *(const float4*)br;
            float4 b1 = *(const float4*)(br + 4);
            *(float4*)&Bs[dr][ec]     = b0;
            *(float4*)&Bs[dr][ec + 4] = b1;
        }
        __syncthreads();
#pragma unroll
        for (int kk = 0; kk < 16; kk++) {
            float a[8];
            *(float4*)(a)     = *(float4*)&As[kk][ty * 8];
            *(float4*)(a + 4) = *(float4*)&As[kk][ty * 8 + 4];
            ulonglong2 bA = *(ulonglong2*)&Bs[kk][tx * 8];
            ulonglong2 bB = *(ulonglong2*)&Bs[kk][tx * 8 + 4];
#pragma unroll
            for (int p = 0; p < 8; p++) {
                ull_t ap; PACK2(ap, a[p], a[p]);
                FMA2(acc2[p][0], ap, bA.x);
                FMA2(acc2[p][1], ap, bA.y);
                FMA2(acc2[p][2], ap, bB.x);
                FMA2(acc2[p][3], ap, bB.y);
            }
        }
        __syncthreads();
    }

#pragma unroll
    for (int ry = 0; ry < 8; ry++) {
        const int m = m0 + ty * 8 + ry;
        const int n = m >> 7, i = m & 127;
        float o[8];
#pragma unroll
        for (int q = 0; q < 4; q++) UNPACK2(o[2*q], o[2*q+1], acc2[ry][q]);
        float* dst = &g_qW[((size_t)(n * 8 + h) * 128 + i) * 512 + e0t + tx * 8];
        *(float4*)dst       = *(float4*)&o[0];
        *(float4*)(dst + 4) = *(float4*)&o[4];
    }
}

// ---------------- K3pre: qk[b][i][j] = q . k  (base logits, unscaled) -------
__global__ __launch_bounds__(256) void k3pre() {
    const int b = blockIdx.x;
    __shared__ float qT[32][128];
    __shared__ float kT[32][128];
    const int t = threadIdx.x, ty = t >> 4, tx = t & 15;

    float acc[8][8];
#pragma unroll
    for (int p = 0; p < 8; p++)
#pragma unroll
        for (int q = 0; q < 8; q++) acc[p][q] = 0.f;

    for (int d0 = 0; d0 < 64; d0 += 32) {
#pragma unroll
        for (int u = 0; u < 4; u++) {
            int ii = (t >> 3) + 32 * u;
            int d4 = (t & 7) * 4;
            float4 a = *(const float4*)&g_q[((size_t)b * 128 + ii) * 64 + d0 + d4];
            qT[d4 + 0][ii] = a.x; qT[d4 + 1][ii] = a.y;
            qT[d4 + 2][ii] = a.z; qT[d4 + 3][ii] = a.w;
            float4 bb = *(const float4*)&g_k[((size_t)b * 128 + ii) * 64 + d0 + d4];
            kT[d4 + 0][ii] = bb.x; kT[d4 + 1][ii] = bb.y;
            kT[d4 + 2][ii] = bb.z; kT[d4 + 3][ii] = bb.w;
        }
        __syncthreads();
#pragma unroll
        for (int d = 0; d < 32; d++) {
            float a[8], bl[8];
            *(float4*)(a)      = *(float4*)&qT[d][ty * 8];
            *(float4*)(a + 4)  = *(float4*)&qT[d][ty * 8 + 4];
            *(float4*)(bl)     = *(float4*)&kT[d][tx * 8];
            *(float4*)(bl + 4) = *(float4*)&kT[d][tx * 8 + 4];
#pragma unroll
            for (int p = 0; p < 8; p++)
#pragma unroll
                for (int q = 0; q < 8; q++) acc[p][q] += a[p] * bl[q];
        }
        __syncthreads();
    }
#pragma unroll
    for (int p = 0; p < 8; p++) {
        float* dst = &g_aw[((size_t)b * 128 + ty * 8 + p) * 128 + tx * 8];
        *(float4*)dst       = *(float4*)&acc[p][0];
        *(float4*)(dst + 4) = *(float4*)&acc[p][4];
    }
}

// ---------------- K34: ONE-PASS logits + exp + s-accum over know ------------
// TJ=16, double-buffered cp.async.
// Phase1: warp (hg, jq) owns 4 heads x full 512e (qW in 32 ull regs), 4 j/tile.
//   Single 4-value butterfly -> final logit -> inline exp -> p_s/pT2. 2 bar/tile.
// Phase3: all 256 threads accumulate s from same smem tile.
#define TJ 16
__global__ __launch_bounds__(256, 2) void k34_onepass(const float* __restrict__ know,
                                                      const int* __restrict__ mask) {
    __shared__ float kn_s[2][TJ][512];   // 64 KB (double buffer)
    __shared__ ull_t pT2[TJ][8];         // 1 KB  (packed (p,p))
    __shared__ float pq_s[8][128];       // 4 KB  (qk base -> unnormalized p)
    __shared__ unsigned char m8[8][128]; // 1 KB
    __shared__ float inv_s[8];

    const int n = blockIdx.x >> 7;
    const int i = blockIdx.x & 127;
    const int t = threadIdx.x, w = t >> 5, l = t & 31;
    const int hg = w & 1, jq = w >> 1;           // phase-1 warp role
    const int h0 = hg * 4;
    const int g = t >> 7;                        // phase-3 h-group (0/1)
    const int e0 = (t & 127) << 2;               // phase-3 e-chunk

    // ---- preload q.k base (into pq_s) + mask ----
    {
        int h = t >> 5, j0 = (t & 31) << 2;
        *(float4*)&pq_s[h][j0] =
            *(const float4*)&g_aw[(((size_t)(n * 8 + h) * 128 + i)) * 128 + j0];
        int4 mm = *(const int4*)&mask[(((size_t)(n * 8 + h) * 128 + i)) * 128 + j0];
        uchar4 mb;
        mb.x = (unsigned char)(mm.x != 0); mb.y = (unsigned char)(mm.y != 0);
        mb.z = (unsigned char)(mm.z != 0); mb.w = (unsigned char)(mm.w != 0);
        *(uchar4*)&m8[h][j0] = mb;
    }

    // ---- qW slices into registers: 4 heads x full 512e, e = 4l + 128u ----
    ulonglong2 qw[4][4];
#pragma unroll
    for (int h = 0; h < 4; h++) {
        const float* qb = &g_qW[(((size_t)(n * 8 + h0 + h) * 128 + i)) * 512 + 4 * l];
#pragma unroll
        for (int u = 0; u < 4; u++)
            qw[h][u] = *(const ulonglong2*)(qb + 128 * u);
    }

    const float* knbase = know + ((size_t)n * 16384 + (size_t)i * 128) * 512;
    const uint32_t kn_sa = (uint32_t)__cvta_generic_to_shared(&kn_s[0][0][0]);

    // persistent s accumulators: heads [4g,4g+4) at e-chunk e0 (e-pairs packed)
    ull_t accv[4][2];
#pragma unroll
    for (int hh = 0; hh < 4; hh++) { accv[hh][0] = 0ull; accv[hh][1] = 0ull; }

    // ---- prologue: stage tile 0 into buf 0 via cp.async ----
#pragma unroll
    for (int u = 0; u < 8; u++) {
        int c = t + 256 * u;
        int r = c >> 7, ch = c & 127;
        cpa16(kn_sa + (uint32_t)(r * 2048 + ch * 16),
              knbase + (size_t)r * 512 + ch * 4);
    }
    cpa_commit();

    int buf = 0;
#pragma unroll 1
    for (int tt = 0; tt < 8; tt++) {
        cpa_wait_all();
        __syncthreads();   // tile[buf] visible; prev phase3 done with pT2

        // stage next tile into buf^1 (overlaps all compute below)
        if (tt < 7) {
            const float* nb = knbase + (size_t)(tt + 1) * TJ * 512;
            const uint32_t sb = kn_sa + (uint32_t)((buf ^ 1) * TJ * 2048);
#pragma unroll
            for (int u = 0; u < 8; u++) {
                int c = t + 256 * u;
                int r = c >> 7, ch = c & 127;
                cpa16(sb + (uint32_t)(r * 2048 + ch * 16),
                      nb + (size_t)r * 512 + ch * 4);
            }
            cpa_commit();
        }

        // ---- phase 1: full logits, inline exp; warp does 4 j rows ----
#pragma unroll
        for (int jj = 0; jj < 4; jj++) {
            const int jl = jq * 4 + jj;
            const int j = tt * TJ + jl;
            ulonglong2 kv[4];
#pragma unroll
            for (int u = 0; u < 4; u++)
                kv[u] = *(const ulonglong2*)&kn_s[buf][jl][4 * l + 128 * u];
            ull_t a2[4];
#pragma unroll
            for (int h = 0; h < 4; h++) a2[h] = 0ull;
#pragma unroll
            for (int h = 0; h < 4; h++)
#pragma unroll
                for (int u = 0; u < 4; u++) {
                    FMA2(a2[h], kv[u].x, qw[h][u].x);
                    FMA2(a2[h], kv[u].y, qw[h][u].y);
                }
            float v[4];
#pragma unroll
            for (int h = 0; h < 4; h++) {
                float lo, hi; UNPACK2(lo, hi, a2[h]); v[h] = lo + hi;
            }
            // value-halving butterfly: 4 vals over 32 lanes
#pragma unroll
            for (int h = 0; h < 2; h++) {
                float give = (l & 16) ? v[h] : v[h + 2];
                float keep = (l & 16) ? v[h + 2] : v[h];
                v[h] = keep + __shfl_xor_sync(0xffffffffu, give, 16);
            }
            {
                float give = (l & 8) ? v[0] : v[1];
                float keep = (l & 8) ? v[1] : v[0];
                v[0] = keep + __shfl_xor_sync(0xffffffffu, give, 8);
            }
            v[0] += __shfl_xor_sync(0xffffffffu, v[0], 4);
            v[0] += __shfl_xor_sync(0xffffffffu, v[0], 2);
            v[0] += __shfl_xor_sync(0xffffffffu, v[0], 1);
            if ((l & 7) == 0) {
                const int h = h0 + ((l >> 4) & 1) * 2 + ((l >> 3) & 1);
                float lg = (v[0] + pq_s[h][j]) * SCALING;
                float p = m8[h][j] ? __expf(lg) : 0.f;
                pq_s[h][j] = p;
                ull_t p2; PACK2(p2, p, p);
                pT2[jl][h] = p2;
            }
        }
        __syncthreads();   // p ready

        // ---- phase 3: s accumulation from same tile ----
        {
            const int h0p = g * 4;
#pragma unroll
            for (int jl = 0; jl < TJ; jl++) {
                ulonglong2 kv = *(const ulonglong2*)&kn_s[buf][jl][e0];
                ulonglong2 pa = *(const ulonglong2*)&pT2[jl][h0p];
                ulonglong2 pb = *(const ulonglong2*)&pT2[jl][h0p + 2];
                FMA2(accv[0][0], pa.x, kv.x); FMA2(accv[0][1], pa.x, kv.y);
                FMA2(accv[1][0], pa.y, kv.x); FMA2(accv[1][1], pa.y, kv.y);
                FMA2(accv[2][0], pb.x, kv.x); FMA2(accv[2][1], pb.x, kv.y);
                FMA2(accv[3][0], pb.y, kv.x); FMA2(accv[3][1], pb.y, kv.y);
            }
        }
        buf ^= 1;
    }

    // ---- normalization: warp w sums p over head w ----
    {
        float s = 0.f;
#pragma unroll
        for (int c = 0; c < 4; c++) s += pq_s[w][l + 32 * c];
#pragma unroll
        for (int off = 16; off; off >>= 1)
            s += __shfl_xor_sync(0xffffffffu, s, off);
        if (l == 0) inv_s[w] = 1.f / s;
    }
    __syncthreads();

    // ---- write s (normalized) ----
    {
        const int h0p = g * 4;
#pragma unroll
        for (int hh = 0; hh < 4; hh++) {
            float inv = inv_s[h0p + hh];
            float4 o;
            UNPACK2(o.x, o.y, accv[hh][0]);
            UNPACK2(o.z, o.w, accv[hh][1]);
            o.x *= inv; o.y *= inv; o.z *= inv; o.w *= inv;
            *(float4*)&g_s[(((size_t)(n * 8 + h0p + hh) * 128 + i)) * 512 + e0] = o;
        }
    }
    // ---- write normalized aw ----
#pragma unroll
    for (int u = 0; u < 4; u++) {
        int c = t + 256 * u;
        int h = c >> 7, j = c & 127;
        g_aw[(((size_t)(n * 8 + h) * 128 + i)) * 128 + j] = pq_s[h][j] * inv_s[h];
    }
}

// ---------------- K4b: attn = aw@v + s@Wknow_h^T  (combined K=640 GEMM) -----
__global__ __launch_bounds__(256) void k4b_attn(const float* __restrict__ Wknow) {
    __shared__ float As[16][64];
    __shared__ float Bs[16][64];
    const int h = blockIdx.y;
    const int r0 = blockIdx.x * 64;
    const int n = r0 >> 7;
    const int i0 = r0 & 127;
    const int t = threadIdx.x;
    const int ty = t >> 4, tx = t & 15;

    ull_t acc2[4][2];
#pragma unroll
    for (int a = 0; a < 4; a++) { acc2[a][0] = 0ull; acc2[a][1] = 0ull; }

    for (int k0 = 0; k0 < 640; k0 += 16) {
        {
            const int rr = t >> 2, kq = (t & 3) * 4;
            const int ii = i0 + rr;
            float4 a4;
            if (k0 < 128)
                a4 = *(const float4*)&g_aw[((size_t)(n * 8 + h) * 128 + ii) * 128 + k0 + kq];
            else
                a4 = *(const float4*)&g_s[((size_t)(n * 8 + h) * 128 + ii) * 512 + (k0 - 128) + kq];
            As[kq + 0][rr] = a4.x; As[kq + 1][rr] = a4.y;
            As[kq + 2][rr] = a4.z; As[kq + 3][rr] = a4.w;
        }
        if (k0 < 128) {
            const int kr = t >> 4, dq = (t & 15) * 4;
            float4 b4 = *(const float4*)&g_v[((size_t)(n * 8 + h) * 128 + (k0 + kr)) * 64 + dq];
            *(float4*)&Bs[kr][dq] = b4;
        } else {
            const int d = t >> 2, eq = (t & 3) * 4;
            float4 w4 = *(const float4*)(Wknow + (size_t)(h * 64 + d) * 512 + (k0 - 128) + eq);
            Bs[eq + 0][d] = w4.x; Bs[eq + 1][d] = w4.y;
            Bs[eq + 2][d] = w4.z; Bs[eq + 3][d] = w4.w;
        }
        __syncthreads();
#pragma unroll
        for (int kk = 0; kk < 16; kk++) {
            float4 a4 = *(float4*)&As[kk][ty * 4];
            ulonglong2 b2 = *(ulonglong2*)&Bs[kk][tx * 4];
            ull_t ap;
            PACK2(ap, a4.x, a4.x); FMA2(acc2[0][0], ap, b2.x); FMA2(acc2[0][1], ap, b2.y);
            PACK2(ap, a4.y, a4.y); FMA2(acc2[1][0], ap, b2.x); FMA2(acc2[1][1], ap, b2.y);
            PACK2(ap, a4.z, a4.z); FMA2(acc2[2][0], ap, b2.x); FMA2(acc2[2][1], ap, b2.y);
            PACK2(ap, a4.w, a4.w); FMA2(acc2[3][0], ap, b2.x); FMA2(acc2[3][1], ap, b2.y);
        }
        __syncthreads();
    }
#pragma unroll
    for (int ry = 0; ry < 4; ry++) {
        const int ii = i0 + ty * 4 + ry;
        float4 o;
        UNPACK2(o.x, o.y, acc2[ry][0]);
        UNPACK2(o.z, o.w, acc2[ry][1]);
        float* dst = g_attn + ((size_t)ii * 16 + n) * 512 + h * 64 + tx * 4;
        *(float4*)dst = o;
    }
}

// ---------------- K5: gating  out = g*r + (1-g)*attn ------------------------
__global__ __launch_bounds__(128) void k5_gate(const float* __restrict__ Wbeta,
                                               float* __restrict__ out) {
    const int m = blockIdx.x;
    const int t = threadIdx.x;
    const int w = t >> 5, l = t & 31;
    __shared__ float red[4];

    const float* a = g_attn + (size_t)m * 512;
    const float* r = g_r + (size_t)m * 512;

    float z = 0.f;
#pragma unroll
    for (int c = 0; c < 4; c++) {
        int e = t + 128 * c;
        float av = a[e], rv = r[e];
        z += Wbeta[e] * av + Wbeta[512 + e] * rv + Wbeta[1024 + e] * (av - rv);
    }
#pragma unroll
    for (int off = 16; off; off >>= 1)
        z += __shfl_xor_sync(0xffffffffu, z, off);
    if (l == 0) red[w] = z;
    __syncthreads();
    float zt = red[0] + red[1] + red[2] + red[3];
    float g = 1.f / (1.f + __expf(-zt));

#pragma unroll
    for (int c = 0; c < 4; c++) {
        int e = t + 128 * c;
        out[(size_t)m * 512 + e] = g * r[e] + (1.f - g) * a[e];
    }
}

// ---------------- launch -----------------------------------------------------
extern "C" void kernel_launch(void* const* d_in, const int* in_sizes, int n_in,
                              void* d_out, int out_size) {
    const float* x     = (const float*)d_in[0];
    const float* know  = (const float*)d_in[1];
    const int*   mask  = (const int*)d_in[2];
    const float* Wq    = (const float*)d_in[3];
    const float* Wk    = (const float*)d_in[4];
    const float* Wv    = (const float*)d_in[5];
    const float* Wknow = (const float*)d_in[6];
    const float* Wskip = (const float*)d_in[7];
    const float* Wbeta = (const float*)d_in[8];
    float* out = (float*)d_out;

    k1_proj<<<dim3(16, 16), 256>>>(x, Wq, Wk, Wv, Wskip);
    k2_qw<<<dim3(64, 8), 256>>>(Wknow);
    k3pre<<<128, 256>>>();
    k34_onepass<<<2048, 256>>>(know, mask);
    k4b_attn<<<dim3(32, 8), 256>>>(Wknow);
    k5_gate<<<2048, 128>>>(Wbeta, out);
}